// round 15
// baseline (speedup 1.0000x reference)
#include <cuda_runtime.h>
#include <cuda_bf16.h>
#include <math.h>
#include <stdint.h>

#define NB 32
#define NCH 512
#define HHH 6
#define WWW 40
#define NPIX 240
#define NCLASS 97
#define NPADC 128
#define TENC 40
#define TDEC 27
#define LLAB 26
#define MENC 1280
#define MDEC 864
#define KCONV 4608
#define MCONV 7680
#define LSTM_BLOCKS 128
#define PRED_Z 4
#define PADW 42
#define PADH 8

__device__ float g_gbuf[MENC*2048];
__device__ float g_seqa[MENC*NCH];
__device__ float g_seqb[MENC*NCH];
__device__ float g_hid[MDEC*NCH];
__device__ float g_hol[NB*NCH];
__device__ float g_q[MDEC*NCH];
__device__ float g_kc[MCONV*NCH];
__device__ float g_pred[PRED_Z*MDEC*NPADC];
__device__ float g_score[NB*TDEC*NPIX];
__device__ __nv_bfloat16 g_padhi[NB*PADH*PADW*NCH];
__device__ __nv_bfloat16 g_padlo[NB*PADH*PADW*NCH];
__device__ __nv_bfloat16 g_kwhi[NCH*KCONV];
__device__ __nv_bfloat16 g_kwlo[NCH*KCONV];
__device__ __nv_bfloat16 g_wihhi[4*2048*NCH];
__device__ __nv_bfloat16 g_wihlo[4*2048*NCH];
__device__ __nv_bfloat16 g_acthi[MENC*NCH];
__device__ __nv_bfloat16 g_actlo[MENC*NCH];
__device__ __nv_bfloat16 g_qwhi[NCH*NCH];
__device__ __nv_bfloat16 g_qwlo[NCH*NCH];
__device__ __nv_bfloat16 g_pwhi[NCLASS*1536];
__device__ __nv_bfloat16 g_pwlo[NCLASS*1536];
__device__ __nv_bfloat16 g_cathi[MDEC*1536];
__device__ __nv_bfloat16 g_catlo[MDEC*1536];
__device__ unsigned g_cnt = 0;
__device__ unsigned g_gen = 0;

// ------------- helpers -------------
__device__ __forceinline__ float mufu_tanh(float x){
    float y; asm("tanh.approx.f32 %0, %1;" : "=f"(y) : "f"(x)); return y;
}
__device__ __forceinline__ float sigm(float x){ return 1.f/(1.f + expf(-x)); }
__device__ __forceinline__ void split2(float v, __nv_bfloat16& h, __nv_bfloat16& l){
    h = __float2bfloat16(v);
    l = __float2bfloat16(v - __bfloat162float(h));
}
__device__ __forceinline__ float psum2(unsigned long long v){
    return __uint_as_float((uint32_t)v) + __uint_as_float((uint32_t)(v >> 32));
}

#define MMA_B16(c, a, b0, b1) asm volatile( \
  "mma.sync.aligned.m16n8k16.row.col.f32.bf16.bf16.f32 " \
  "{%0,%1,%2,%3},{%4,%5,%6,%7},{%8,%9},{%0,%1,%2,%3};\n" \
  : "+f"((c)[0]),"+f"((c)[1]),"+f"((c)[2]),"+f"((c)[3]) \
  : "r"((a)[0]),"r"((a)[1]),"r"((a)[2]),"r"((a)[3]),"r"(b0),"r"(b1))

#define LDSM4(r, addr) asm volatile( \
  "ldmatrix.sync.aligned.m8n8.x4.shared.b16 {%0,%1,%2,%3}, [%4];" \
  : "=r"((r)[0]),"=r"((r)[1]),"=r"((r)[2]),"=r"((r)[3]) : "r"(addr))

#define FMA2(c, a, b) asm("fma.rn.f32x2 %0, %1, %2, %0;" : "+l"(c) : "l"(a), "l"(b))

__device__ __forceinline__ void cp16(uint32_t daddr, const void* src, int srcsz){
    asm volatile("cp.async.cg.shared.global [%0], [%1], 16, %2;\n"
                 :: "r"(daddr), "l"(src), "r"(srcsz));
}

__global__ void cvt_split(const float* __restrict__ x, __nv_bfloat16* __restrict__ hi,
                          __nv_bfloat16* __restrict__ lo, int n){
    int i = blockIdx.x*256 + threadIdx.x;
    if (i < n) split2(x[i], hi[i], lo[i]);
}
__global__ void cvt4(const float* __restrict__ a0, const float* __restrict__ a1,
                     const float* __restrict__ a2, const float* __restrict__ a3,
                     __nv_bfloat16* __restrict__ hi, __nv_bfloat16* __restrict__ lo){
    int which = blockIdx.y;
    const float* src = which == 0 ? a0 : which == 1 ? a1 : which == 2 ? a2 : a3;
    int i = blockIdx.x*256 + threadIdx.x;
    if (i < 2048*NCH) {
        size_t o = (size_t)which*2048*NCH + i;
        split2(src[i], hi[o], lo[o]);
    }
}
__global__ void cvt_kw(const float* __restrict__ kW, __nv_bfloat16* __restrict__ hi,
                       __nv_bfloat16* __restrict__ lo){
    int i = blockIdx.x*256 + threadIdx.x;
    if (i >= NCH*KCONV) return;
    int o = i / KCONV, r = i - o*KCONV;
    int tap = r >> 9, cin = r & 511;
    split2(kW[(size_t)o*KCONV + cin*9 + tap], hi[i], lo[i]);
}
__global__ void featv_kernel(const float* __restrict__ feat,
                             __nv_bfloat16* __restrict__ hi, __nv_bfloat16* __restrict__ lo){
    int idx = blockIdx.x*256 + threadIdx.x;
    if (idx >= NB*NCH*WWW) return;
    int w = idx % WWW;
    int c = (idx / WWW) % NCH;
    int b = idx / (WWW*NCH);
    const float* p = feat + ((size_t)(b*NCH + c)*HHH)*WWW + w;
    float m = p[0];
    #pragma unroll
    for (int h = 1; h < HHH; h++) m = fmaxf(m, p[h*WWW]);
    size_t o = ((size_t)(w*NB + b))*NCH + c;
    split2(m, hi[o], lo[o]);
}

__global__ __launch_bounds__(256) void featpad_kernel(
    const float* __restrict__ feat,
    __nv_bfloat16* __restrict__ hi, __nv_bfloat16* __restrict__ lo)
{
    __shared__ float sm[128*41];
    const int tid = threadIdx.x;
    const int c0 = blockIdx.x * 128;
    const int b  = blockIdx.y >> 3;
    const int yy = blockIdx.y & 7;
    const int y  = yy - 1;
    const bool rowvalid = (y >= 0 && y < HHH);
    if (rowvalid) {
        for (int i = tid; i < 128*WWW; i += 256) {
            int c = i / WWW, x = i - c*WWW;
            sm[c*41 + x] = feat[((size_t)(b*NCH + c0 + c)*HHH + y)*WWW + x];
        }
    }
    __syncthreads();
    for (int i = tid; i < PADW*128; i += 256) {
        int xx = i >> 7, c = i & 127;
        int x = xx - 1;
        float v = (rowvalid && x >= 0 && x < WWW) ? sm[c*41 + x] : 0.f;
        size_t o = ((size_t)((b*PADH + yy)*PADW + xx))*NCH + c0 + c;
        split2(v, hi[o], lo[o]);
    }
}

// ---- tile geometry ----
#define SA_ELEM (128*40)
#define SB_ELEM (64*40)
#define STG_AH 0
#define STG_AL (SA_ELEM*2)
#define STG_BH (2*SA_ELEM*2)
#define STG_BL (2*SA_ELEM*2 + SB_ELEM*2)
#define STAGE_BYTES (2*SA_ELEM*2 + 2*SB_ELEM*2)
#define W_AH 0
#define W_AL (SA_ELEM*2)
#define W_BH (2*SA_ELEM*2)
#define W_BL (3*SA_ELEM*2)
#define WSTAGE_BYTES (4*SA_ELEM*2)
// conv smem padded so exactly 1 CTA/SM and co-residency with lstm_layer (99KB):
// 120000 + 101696 <= 233472.
#define CONV_SMEM 120000

// implicit-conv GEMM: 128x128 tile, 1 CTA/SM (smem-padded). grid (4, 60).
__global__ __launch_bounds__(256) void conv_gemm2(
    const __nv_bfloat16* __restrict__ Ahi, const __nv_bfloat16* __restrict__ Alo,
    const __nv_bfloat16* __restrict__ Bhi, const __nv_bfloat16* __restrict__ Blo,
    float* __restrict__ C, const float* __restrict__ bias)
{
    extern __shared__ __nv_bfloat16 smb[];
    const int tid = threadIdx.x;
    const int lane = tid & 31, warp = tid >> 5;
    const int wm = (warp & 3) << 5;
    const int wn = (warp >> 2) << 6;
    const int m0 = blockIdx.y * 128, n0 = blockIdx.x * 128;
    float acc[2][8][4];
    #pragma unroll
    for (int a = 0; a < 2; a++)
        #pragma unroll
        for (int b = 0; b < 8; b++)
            #pragma unroll
            for (int c = 0; c < 4; c++) acc[a][b][c] = 0.f;

    const uint32_t smemBase = (uint32_t)__cvta_generic_to_shared(smb);
    const int r0 = tid >> 2,          s0 = tid & 3;
    const int r1 = (tid + 256) >> 2,  s1 = (tid + 256) & 3;
    int gm0 = m0 + r0, gm1 = m0 + r1;
    int b0i = gm0 / NPIX, p0i = gm0 - b0i*NPIX, y0 = p0i / WWW, x0 = p0i - y0*WWW;
    int b1i = gm1 / NPIX, p1i = gm1 - b1i*NPIX, y1 = p1i / WWW, x1 = p1i - y1*WWW;
    const int pb0 = (b0i*PADH + y0)*PADW + x0;
    const int pb1 = (b1i*PADH + y1)*PADW + x1;
    const size_t rB0 = (size_t)(n0 + r0)*KCONV;
    const size_t rB1 = (size_t)(n0 + r1)*KCONV;
    const uint32_t d0 = (uint32_t)(r0*40 + s0*8)*2;
    const uint32_t d1 = (uint32_t)(r1*40 + s1*8)*2;
    const int o0 = s0*8, o1 = s1*8;

    const uint32_t aOff = (uint32_t)((wm + (lane & 15))*40 + (lane >> 4)*8)*2;
    const uint32_t bOff = (uint32_t)((wn + (lane & 7) + ((lane >> 4) & 1)*8)*40
                                     + ((lane >> 3) & 1)*8)*2;
    const int KT = KCONV >> 5;

    auto loadStage = [&](int it){
        int k0 = it << 5;
        uint32_t sb = smemBase + (it & 1) * WSTAGE_BYTES;
        int k0a = k0 + o0, k1a = k0 + o1;
        int tap0 = k0a >> 9, cin0 = k0a & 511;
        int tap1 = k1a >> 9, cin1 = k1a & 511;
        int td0 = (tap0*11) >> 5, td1 = (tap1*11) >> 5;
        int tofs0 = td0*PADW + (tap0 - td0*3);
        int tofs1 = td1*PADW + (tap1 - td1*3);
        size_t a0 = (size_t)(pb0 + tofs0)*NCH + cin0;
        size_t a1 = (size_t)(pb1 + tofs1)*NCH + cin1;
        cp16(sb + W_AH + d0, Ahi + a0, 16);
        cp16(sb + W_AH + d1, Ahi + a1, 16);
        cp16(sb + W_AL + d0, Alo + a0, 16);
        cp16(sb + W_AL + d1, Alo + a1, 16);
        cp16(sb + W_BH + d0, Bhi + rB0 + k0 + o0, 16);
        cp16(sb + W_BH + d1, Bhi + rB1 + k0 + o1, 16);
        cp16(sb + W_BL + d0, Blo + rB0 + k0 + o0, 16);
        cp16(sb + W_BL + d1, Blo + rB1 + k0 + o1, 16);
        asm volatile("cp.async.commit_group;\n");
    };

    loadStage(0);
    for (int it = 0; it < KT; it++) {
        if (it + 1 < KT) {
            loadStage(it + 1);
            asm volatile("cp.async.wait_group 1;\n");
        } else {
            asm volatile("cp.async.wait_group 0;\n");
        }
        __syncthreads();
        uint32_t sb = smemBase + (it & 1) * WSTAGE_BYTES;
        #pragma unroll
        for (int s = 0; s < 2; s++) {
            const uint32_t kB = s*32;
            uint32_t ah[2][4], al[2][4];
            LDSM4(ah[0], sb + W_AH + aOff + kB);
            LDSM4(ah[1], sb + W_AH + aOff + 16*80 + kB);
            LDSM4(al[0], sb + W_AL + aOff + kB);
            LDSM4(al[1], sb + W_AL + aOff + 16*80 + kB);
            #pragma unroll
            for (int ntp = 0; ntp < 4; ntp++) {
                uint32_t bh[4], bl[4];
                LDSM4(bh, sb + W_BH + bOff + ntp*16*80 + kB);
                LDSM4(bl, sb + W_BL + bOff + ntp*16*80 + kB);
                #pragma unroll
                for (int mt = 0; mt < 2; mt++) {
                    MMA_B16(acc[mt][2*ntp],   ah[mt], bh[0], bh[1]);
                    MMA_B16(acc[mt][2*ntp],   ah[mt], bl[0], bl[1]);
                    MMA_B16(acc[mt][2*ntp],   al[mt], bh[0], bh[1]);
                    MMA_B16(acc[mt][2*ntp+1], ah[mt], bh[2], bh[3]);
                    MMA_B16(acc[mt][2*ntp+1], ah[mt], bl[2], bl[3]);
                    MMA_B16(acc[mt][2*ntp+1], al[mt], bh[2], bh[3]);
                }
            }
        }
        __syncthreads();
    }
    const int r = lane >> 2, kq = (lane & 3) << 1;
    #pragma unroll
    for (int mt = 0; mt < 2; mt++) {
        #pragma unroll
        for (int nt = 0; nt < 8; nt++) {
            int m = m0 + wm + mt*16 + r;
            int n = n0 + wn + nt*8 + kq;
            float bv0 = bias[n], bv1 = bias[n+1];
            C[(size_t)m*NCH + n]       = acc[mt][nt][0] + bv0;
            C[(size_t)m*NCH + n + 1]   = acc[mt][nt][1] + bv1;
            C[(size_t)(m+8)*NCH + n]   = acc[mt][nt][2] + bv0;
            C[(size_t)(m+8)*NCH + n+1] = acc[mt][nt][3] + bv1;
        }
    }
}

// generic 128x128 GEMM (xW)
__global__ __launch_bounds__(256, 2) void gemm_w(
    const __nv_bfloat16* __restrict__ Ahi, const __nv_bfloat16* __restrict__ Alo,
    const __nv_bfloat16* __restrict__ Bhi, const __nv_bfloat16* __restrict__ Blo,
    float* __restrict__ C, int M, int N, int K,
    const float* __restrict__ bias1, const float* __restrict__ bias2)
{
    extern __shared__ __nv_bfloat16 smb[];
    const int tid = threadIdx.x;
    const int lane = tid & 31, warp = tid >> 5;
    const int wm = (warp & 3) << 5;
    const int wn = (warp >> 2) << 6;
    const int m0 = blockIdx.y * 128, n0 = blockIdx.x * 128;
    float acc[2][8][4];
    #pragma unroll
    for (int a = 0; a < 2; a++)
        #pragma unroll
        for (int b = 0; b < 8; b++)
            #pragma unroll
            for (int c = 0; c < 4; c++) acc[a][b][c] = 0.f;

    const uint32_t smemBase = (uint32_t)__cvta_generic_to_shared(smb);
    const int r0 = tid >> 2,          s0 = tid & 3;
    const int r1 = (tid + 256) >> 2,  s1 = (tid + 256) & 3;
    const int gm0 = m0 + r0, gm1 = m0 + r1;
    const int szA0 = (gm0 < M) ? 16 : 0;
    const int szA1 = (gm1 < M) ? 16 : 0;
    const size_t rA0 = (size_t)min(gm0, M-1)*K, rA1 = (size_t)min(gm1, M-1)*K;
    const size_t rB0 = (size_t)(n0 + r0)*K, rB1 = (size_t)(n0 + r1)*K;
    const uint32_t d0 = (uint32_t)(r0*40 + s0*8)*2;
    const uint32_t d1 = (uint32_t)(r1*40 + s1*8)*2;
    const int o0 = s0*8, o1 = s1*8;
    const uint32_t aOff = (uint32_t)((wm + (lane & 15))*40 + (lane >> 4)*8)*2;
    const uint32_t bOff = (uint32_t)((wn + (lane & 7) + ((lane >> 4) & 1)*8)*40
                                     + ((lane >> 3) & 1)*8)*2;
    const int KT = K >> 5;

    auto loadStage = [&](int it){
        int k0 = it << 5;
        uint32_t sb = smemBase + (it & 1) * WSTAGE_BYTES;
        cp16(sb + W_AH + d0, Ahi + rA0 + k0 + o0, szA0);
        cp16(sb + W_AH + d1, Ahi + rA1 + k0 + o1, szA1);
        cp16(sb + W_AL + d0, Alo + rA0 + k0 + o0, szA0);
        cp16(sb + W_AL + d1, Alo + rA1 + k0 + o1, szA1);
        cp16(sb + W_BH + d0, Bhi + rB0 + k0 + o0, 16);
        cp16(sb + W_BH + d1, Bhi + rB1 + k0 + o1, 16);
        cp16(sb + W_BL + d0, Blo + rB0 + k0 + o0, 16);
        cp16(sb + W_BL + d1, Blo + rB1 + k0 + o1, 16);
        asm volatile("cp.async.commit_group;\n");
    };

    loadStage(0);
    for (int it = 0; it < KT; it++) {
        if (it + 1 < KT) {
            loadStage(it + 1);
            asm volatile("cp.async.wait_group 1;\n");
        } else {
            asm volatile("cp.async.wait_group 0;\n");
        }
        __syncthreads();
        uint32_t sb = smemBase + (it & 1) * WSTAGE_BYTES;
        #pragma unroll
        for (int s = 0; s < 2; s++) {
            const uint32_t kB = s*32;
            uint32_t ah[2][4], al[2][4];
            LDSM4(ah[0], sb + W_AH + aOff + kB);
            LDSM4(ah[1], sb + W_AH + aOff + 16*80 + kB);
            LDSM4(al[0], sb + W_AL + aOff + kB);
            LDSM4(al[1], sb + W_AL + aOff + 16*80 + kB);
            #pragma unroll
            for (int ntp = 0; ntp < 4; ntp++) {
                uint32_t bh[4], bl[4];
                LDSM4(bh, sb + W_BH + bOff + ntp*16*80 + kB);
                LDSM4(bl, sb + W_BL + bOff + ntp*16*80 + kB);
                #pragma unroll
                for (int mt = 0; mt < 2; mt++) {
                    MMA_B16(acc[mt][2*ntp],   ah[mt], bh[0], bh[1]);
                    MMA_B16(acc[mt][2*ntp],   ah[mt], bl[0], bl[1]);
                    MMA_B16(acc[mt][2*ntp],   al[mt], bh[0], bh[1]);
                    MMA_B16(acc[mt][2*ntp+1], ah[mt], bh[2], bh[3]);
                    MMA_B16(acc[mt][2*ntp+1], ah[mt], bl[2], bl[3]);
                    MMA_B16(acc[mt][2*ntp+1], al[mt], bh[2], bh[3]);
                }
            }
        }
        __syncthreads();
    }
    const int r = lane >> 2, kq = (lane & 3) << 1;
    #pragma unroll
    for (int mt = 0; mt < 2; mt++) {
        #pragma unroll
        for (int nt = 0; nt < 8; nt++) {
            int m = m0 + wm + mt*16 + r;
            int n = n0 + wn + nt*8 + kq;
            float bv0 = 0.f, bv1 = 0.f;
            if (bias1) { bv0 += bias1[n]; bv1 += bias1[n+1]; }
            if (bias2) { bv0 += bias2[n]; bv1 += bias2[n+1]; }
            if (m < M) {
                C[(size_t)m*N + n]     = acc[mt][nt][0] + bv0;
                C[(size_t)m*N + n + 1] = acc[mt][nt][1] + bv1;
            }
            if (m + 8 < M) {
                C[(size_t)(m+8)*N + n]     = acc[mt][nt][2] + bv0;
                C[(size_t)(m+8)*N + n + 1] = acc[mt][nt][3] + bv1;
            }
        }
    }
}

// 128x64 GEMM (q, pred). B-row guard + split-K via gridDim.z.
__global__ __launch_bounds__(256) void mma_gemm(
    const __nv_bfloat16* __restrict__ Ahi, const __nv_bfloat16* __restrict__ Alo,
    const __nv_bfloat16* __restrict__ Bhi, const __nv_bfloat16* __restrict__ Blo,
    float* __restrict__ C, int M, int N, int K, int NBrows,
    const float* __restrict__ bias1, const float* __restrict__ bias2)
{
    extern __shared__ __nv_bfloat16 smb[];
    const int tid = threadIdx.x;
    const int lane = tid & 31, warp = tid >> 5;
    const int wm = (warp & 3) << 5;
    const int wn = (warp >> 2) << 5;
    const int m0 = blockIdx.y * 128, n0 = blockIdx.x * 64;
    const int Kc = K / gridDim.z;
    const int kbeg = blockIdx.z * Kc;
    float acc[2][4][4];
    #pragma unroll
    for (int a = 0; a < 2; a++)
        #pragma unroll
        for (int b = 0; b < 4; b++)
            #pragma unroll
            for (int c = 0; c < 4; c++) acc[a][b][c] = 0.f;

    const uint32_t smemBase = (uint32_t)__cvta_generic_to_shared(smb);
    const int ar0 = tid >> 2,         as0 = tid & 3;
    const int ar1 = (tid + 256) >> 2, as1 = (tid + 256) & 3;
    const int br  = tid >> 2,         bs  = tid & 3;
    const int gm0 = m0 + ar0, gm1 = m0 + ar1, gn = n0 + br;
    const int szA0 = (gm0 < M) ? 16 : 0;
    const int szA1 = (gm1 < M) ? 16 : 0;
    const int szB  = (gn < NBrows) ? 16 : 0;
    const size_t rA0 = (size_t)min(gm0, M-1)*K, rA1 = (size_t)min(gm1, M-1)*K;
    const size_t rB  = (size_t)min(gn, NBrows-1)*K;
    const uint32_t dA0 = (uint32_t)(ar0*40 + as0*8)*2;
    const uint32_t dA1 = (uint32_t)(ar1*40 + as1*8)*2;
    const uint32_t dB  = (uint32_t)(br*40 + bs*8)*2;
    const int oA0 = as0*8, oA1 = as1*8, oB = bs*8;
    const uint32_t aOff = (uint32_t)((wm + (lane & 15))*40 + (lane >> 4)*8)*2;
    const uint32_t bOff = (uint32_t)((wn + (lane & 7) + ((lane >> 4) & 1)*8)*40
                                     + ((lane >> 3) & 1)*8)*2;
    const int KT = Kc >> 5;
    {
        uint32_t sb = smemBase;
        cp16(sb + STG_AH + dA0, Ahi + rA0 + kbeg + oA0, szA0);
        cp16(sb + STG_AH + dA1, Ahi + rA1 + kbeg + oA1, szA1);
        cp16(sb + STG_AL + dA0, Alo + rA0 + kbeg + oA0, szA0);
        cp16(sb + STG_AL + dA1, Alo + rA1 + kbeg + oA1, szA1);
        cp16(sb + STG_BH + dB,  Bhi + rB  + kbeg + oB,  szB);
        cp16(sb + STG_BL + dB,  Blo + rB  + kbeg + oB,  szB);
        asm volatile("cp.async.commit_group;\n");
    }
    for (int it = 0; it < KT; it++) {
        if (it + 1 < KT) {
            int k0 = kbeg + ((it + 1) << 5);
            uint32_t sb = smemBase + ((it + 1) & 1) * STAGE_BYTES;
            cp16(sb + STG_AH + dA0, Ahi + rA0 + k0 + oA0, szA0);
            cp16(sb + STG_AH + dA1, Ahi + rA1 + k0 + oA1, szA1);
            cp16(sb + STG_AL + dA0, Alo + rA0 + k0 + oA0, szA0);
            cp16(sb + STG_AL + dA1, Alo + rA1 + k0 + oA1, szA1);
            cp16(sb + STG_BH + dB,  Bhi + rB  + k0 + oB,  szB);
            cp16(sb + STG_BL + dB,  Blo + rB  + k0 + oB,  szB);
            asm volatile("cp.async.commit_group;\n");
            asm volatile("cp.async.wait_group 1;\n");
        } else {
            asm volatile("cp.async.wait_group 0;\n");
        }
        __syncthreads();
        uint32_t sb = smemBase + (it & 1) * STAGE_BYTES;
        #pragma unroll
        for (int s = 0; s < 2; s++) {
            const uint32_t kB = s*32;
            uint32_t ah[2][4], al[2][4];
            LDSM4(ah[0], sb + STG_AH + aOff + kB);
            LDSM4(ah[1], sb + STG_AH + aOff + 16*80 + kB);
            LDSM4(al[0], sb + STG_AL + aOff + kB);
            LDSM4(al[1], sb + STG_AL + aOff + 16*80 + kB);
            #pragma unroll
            for (int ntp = 0; ntp < 2; ntp++) {
                uint32_t bh[4], bl[4];
                LDSM4(bh, sb + STG_BH + bOff + ntp*16*80 + kB);
                LDSM4(bl, sb + STG_BL + bOff + ntp*16*80 + kB);
                #pragma unroll
                for (int mt = 0; mt < 2; mt++) {
                    MMA_B16(acc[mt][2*ntp],   ah[mt], bh[0], bh[1]);
                    MMA_B16(acc[mt][2*ntp],   ah[mt], bl[0], bl[1]);
                    MMA_B16(acc[mt][2*ntp],   al[mt], bh[0], bh[1]);
                    MMA_B16(acc[mt][2*ntp+1], ah[mt], bh[2], bh[3]);
                    MMA_B16(acc[mt][2*ntp+1], ah[mt], bl[2], bl[3]);
                    MMA_B16(acc[mt][2*ntp+1], al[mt], bh[2], bh[3]);
                }
            }
        }
        __syncthreads();
    }
    float* Co = C + (size_t)blockIdx.z * M * N;
    const bool addb = (blockIdx.z == 0);
    const int r = lane >> 2, kq = (lane & 3) << 1;
    #pragma unroll
    for (int mt = 0; mt < 2; mt++) {
        #pragma unroll
        for (int nt = 0; nt < 4; nt++) {
            int m = m0 + wm + mt*16 + r;
            int n = n0 + wn + nt*8 + kq;
            float bv0 = 0.f, bv1 = 0.f;
            if (addb && bias1) {
                if (n < NBrows)     bv0 += bias1[n];
                if (n + 1 < NBrows) bv1 += bias1[n+1];
            }
            if (addb && bias2) {
                if (n < NBrows)     bv0 += bias2[n];
                if (n + 1 < NBrows) bv1 += bias2[n+1];
            }
            if (m < M) {
                Co[(size_t)m*N + n]     = acc[mt][nt][0] + bv0;
                Co[(size_t)m*N + n + 1] = acc[mt][nt][1] + bv1;
            }
            if (m + 8 < M) {
                Co[(size_t)(m+8)*N + n]     = acc[mt][nt][2] + bv0;
                Co[(size_t)(m+8)*N + n + 1] = acc[mt][nt][3] + bv1;
            }
        }
    }
}

__global__ __launch_bounds__(256) void holistic_kernel(
    const float* __restrict__ A, const float* __restrict__ W,
    const float* __restrict__ bias, float* __restrict__ C)
{
    extern __shared__ float sm[];
    float* sA = sm;
    float* sW = sm + 32*513;
    float* sP = sW + 4*512;
    const int tid = threadIdx.x;
    const int j0 = blockIdx.x * 4;
    for (int i = tid; i < 32*512; i += 256)
        sA[(i>>9)*513 + (i&511)] = A[i];
    for (int i = tid; i < 4*512; i += 256)
        sW[i] = W[(size_t)(j0 + (i>>9))*512 + (i&511)];
    __syncthreads();
    const int bb = tid & 31, jq = (tid>>5)&3, kh = tid>>7;
    const float* ar = sA + bb*513 + kh*256;
    const float* wr = sW + jq*512 + kh*256;
    float acc = 0.f;
    #pragma unroll 8
    for (int k = 0; k < 256; k++) acc = fmaf(ar[k], wr[k], acc);
    sP[tid] = acc;
    __syncthreads();
    if (kh == 0) C[bb*512 + j0 + jq] = sP[tid] + sP[tid+128] + bias[j0+jq];
}

// persistent LSTM layer (FFMA2, gpre prefetch)
__global__ __launch_bounds__(256) void lstm_layer(
    const float* __restrict__ gpre, const float* __restrict__ Whh,
    float* __restrict__ seq, int T,
    __nv_bfloat16* __restrict__ ohi, __nv_bfloat16* __restrict__ olo)
{
    extern __shared__ float sm[];
    float* sW  = sm;
    float* sh  = sm + 16*516;
    float* gex = sm + 16*516 + 32*516;
    float* sc  = gex + 16*33;
    const int tid = threadIdx.x;
    const int j0 = blockIdx.x * 4;
    #pragma unroll
    for (int rr = 0; rr < 16; rr++) {
        int grow = (rr & 3)*512 + j0 + (rr >> 2);
        for (int k = tid*4; k < 512; k += 1024) {
            float4 v = *(const float4*)(Whh + (size_t)grow*512 + k);
            *(float4*)&sW[rr*516 + k] = v;
        }
    }
    if (tid < 128) sc[tid] = 0.f;
    __syncthreads();
    const int row = tid & 15;
    const int b0  = tid >> 4;
    const int b1  = b0 + 16;
    const int cu  = tid & 3, cb = tid >> 2;
    const int cj  = j0 + cu;
    for (int t = 0; t < T; t++) {
        float gpi = 0.f, gpf = 0.f, gpg = 0.f, gpo = 0.f;
        if (tid < 128) {
            const float* gp = gpre + ((size_t)t*NB + cb)*2048;
            gpi = gp[cj]; gpf = gp[512 + cj]; gpg = gp[1024 + cj]; gpo = gp[1536 + cj];
        }
        float acc0 = 0.f, acc1 = 0.f;
        if (t > 0) {
            const float* hp = seq + (size_t)(t-1)*NB*NCH;
            #pragma unroll
            for (int j = 0; j < 16; j++) {
                int v = tid + j*256;
                int bb = v >> 7, k4 = (v & 127) << 2;
                float4 x = __ldcg((const float4*)(hp + bb*512 + k4));
                *(float4*)&sh[bb*516 + k4] = x;
            }
            __syncthreads();
            unsigned long long a0x = 0ull, a0y = 0ull, a1x = 0ull, a1y = 0ull;
            #pragma unroll 4
            for (int k = 0; k < 512; k += 4) {
                ulonglong2 w  = *(const ulonglong2*)&sW[row*516 + k];
                ulonglong2 h0 = *(const ulonglong2*)&sh[b0*516 + k];
                ulonglong2 h1 = *(const ulonglong2*)&sh[b1*516 + k];
                FMA2(a0x, w.x, h0.x); FMA2(a0y, w.y, h0.y);
                FMA2(a1x, w.x, h1.x); FMA2(a1y, w.y, h1.y);
            }
            acc0 = psum2(a0x) + psum2(a0y);
            acc1 = psum2(a1x) + psum2(a1y);
        }
        gex[row*33 + b0] = acc0;
        gex[row*33 + b1] = acc1;
        __syncthreads();
        if (tid < 128) {
            float gi = gex[(cu*4+0)*33 + cb] + gpi;
            float gf = gex[(cu*4+1)*33 + cb] + gpf;
            float gg = gex[(cu*4+2)*33 + cb] + gpg;
            float go = gex[(cu*4+3)*33 + cb] + gpo;
            float c = sigm(gf)*sc[cu*32+cb] + sigm(gi)*tanhf(gg);
            sc[cu*32+cb] = c;
            float hv = sigm(go)*tanhf(c);
            size_t oo = (size_t)t*NB*NCH + cb*512 + cj;
            seq[oo] = hv;
            if (ohi) split2(hv, ohi[oo], olo[oo]);
        }
        if (t < T-1) {
            __syncthreads();
            if (tid == 0) {
                __threadfence();
                unsigned old = *((volatile unsigned*)&g_gen);
                __threadfence();
                unsigned n = atomicAdd(&g_cnt, 1u);
                if (n == LSTM_BLOCKS-1) {
                    g_cnt = 0;
                    __threadfence();
                    atomicAdd(&g_gen, 1u);
                } else {
                    while (*((volatile unsigned*)&g_gen) == old) { }
                }
            }
            __syncthreads();
        }
    }
}

__global__ void tok_kernel(const float* __restrict__ hol, const float* __restrict__ emb,
                           const int* __restrict__ label,
                           __nv_bfloat16* __restrict__ hi, __nv_bfloat16* __restrict__ lo){
    int row = blockIdx.x;
    int b = row & 31, t = row >> 5;
    const float* src = (t == 0) ? (hol + b*NCH)
                                : (emb + (size_t)label[b*LLAB + (t-1)]*NCH);
    for (int i = threadIdx.x; i < NCH; i += 256) {
        size_t o = (size_t)row*NCH + i;
        split2(src[i], hi[o], lo[o]);
    }
}

// scores: MUFU tanh
__global__ __launch_bounds__(256) void score_kernel(
    const float* __restrict__ kc, const float* __restrict__ qm,
    const float* __restrict__ sW, const float* __restrict__ sb,
    float* __restrict__ score)
{
    extern __shared__ float sm[];
    float* qs  = sm;
    float* sws = sm + 27*512;
    float* kcr = sws + 512;
    const int b  = blockIdx.y;
    const int p0 = blockIdx.x * 12;
    const int tid = threadIdx.x;
    const int lane = tid & 31, w = tid >> 5;
    for (int i = tid; i < 27*512; i += 256) {
        int t = i >> 9, c = i & 511;
        qs[i] = qm[((size_t)(t*32+b))*512 + c];
    }
    for (int i = tid; i < 512; i += 256) sws[i] = sW[i];
    __syncthreads();
    const float sbv = sb[0];
    for (int pp = 0; pp < 12; pp++) {
        int p = p0 + pp;
        for (int i = tid; i < 512; i += 256)
            kcr[i] = kc[((size_t)(b*NPIX + p))*512 + i];
        __syncthreads();
        for (int t = w; t < TDEC; t += 8) {
            float s = 0.f;
            const float* qrow = qs + t*512;
            #pragma unroll
            for (int i = 0; i < 16; i++) {
                int c = lane + i*32;
                s = fmaf(sws[c], mufu_tanh(kcr[c] + qrow[c]), s);
            }
            #pragma unroll
            for (int o = 16; o; o >>= 1) s += __shfl_xor_sync(0xffffffffu, s, o);
            if (lane == 0) score[((size_t)(b*TDEC) + t)*NPIX + p] = s + sbv;
        }
        __syncthreads();
    }
}

__global__ __launch_bounds__(256) void softmax_kernel(
    float* __restrict__ score, const float* __restrict__ hid,
    const float* __restrict__ hol, const float* __restrict__ vr,
    __nv_bfloat16* __restrict__ cathi, __nv_bfloat16* __restrict__ catlo)
{
    __shared__ float sc[TDEC*NPIX];
    const int b = blockIdx.x;
    const int tid = threadIdx.x;
    const int lane = tid & 31, w = tid >> 5;
    int vw = min(WWW, (int)ceilf(WWW * vr[b]));
    for (int i = tid; i < TDEC*NPIX; i += 256) {
        int p = i % NPIX;
        float v = score[(size_t)b*TDEC*NPIX + i];
        sc[i] = ((p % WWW) < vw) ? v : -1e30f;
    }
    __syncthreads();
    for (int t = w; t < TDEC; t += 8) {
        float m = -1e30f;
        for (int p = lane; p < NPIX; p += 32) m = fmaxf(m, sc[t*NPIX + p]);
        #pragma unroll
        for (int o = 16; o; o >>= 1) m = fmaxf(m, __shfl_xor_sync(0xffffffffu, m, o));
        float s = 0.f;
        for (int p = lane; p < NPIX; p += 32) {
            float e = __expf(sc[t*NPIX + p] - m);
            sc[t*NPIX + p] = e;
            s += e;
        }
        #pragma unroll
        for (int o = 16; o; o >>= 1) s += __shfl_xor_sync(0xffffffffu, s, o);
        float inv = 1.f / s;
        for (int p = lane; p < NPIX; p += 32)
            score[(size_t)b*TDEC*NPIX + t*NPIX + p] = sc[t*NPIX + p] * inv;
    }
    for (int i = tid; i < TDEC*512; i += 256) {
        int t = i >> 9, c = i & 511;
        size_t row = (size_t)(t*32 + b);
        split2(hid[row*512 + c], cathi[row*1536 + c], catlo[row*1536 + c]);
        split2(hol[b*512 + c], cathi[row*1536 + 1024 + c], catlo[row*1536 + 1024 + c]);
    }
}

__global__ __launch_bounds__(256) void attnfeat_kernel(
    const float* __restrict__ score, const float* __restrict__ feat,
    __nv_bfloat16* __restrict__ cathi, __nv_bfloat16* __restrict__ catlo)
{
    extern __shared__ float sm[];
    float* aw  = sm;
    float* fch = sm + TDEC*NPIX;
    const int b = blockIdx.y;
    const int c0 = blockIdx.x * 64;
    const int tid = threadIdx.x;
    for (int i = tid; i < TDEC*NPIX; i += 256)
        aw[i] = score[(size_t)b*TDEC*NPIX + i];
    for (int i = tid; i < 64*NPIX; i += 256) {
        int c = i / NPIX, p = i - c*NPIX;
        fch[c*241 + p] = feat[((size_t)(b*NCH + c0 + c))*NPIX + p];
    }
    __syncthreads();
    for (int task = tid; task < TDEC*64; task += 256) {
        int t = task >> 6, c = task & 63;
        float acc = 0.f;
        const float* ar = aw + t*NPIX;
        const float* fr = fch + c*241;
        #pragma unroll 4
        for (int p = 0; p < NPIX; p++) acc = fmaf(ar[p], fr[p], acc);
        size_t o = ((size_t)(t*32 + b))*1536 + 512 + c0 + c;
        split2(acc, cathi[o], catlo[o]);
    }
}

__global__ void out_kernel(const float* __restrict__ pred, float* __restrict__ out){
    int idx = blockIdx.x*256 + threadIdx.x;
    if (idx >= NB*LLAB*NCLASS) return;
    int n  = idx % NCLASS;
    int t1 = (idx / NCLASS) % LLAB;
    int b  = idx / (NCLASS*LLAB);
    size_t row = (size_t)((t1+1)*NB + b)*NPADC + n;
    float s = 0.f;
    #pragma unroll
    for (int z = 0; z < PRED_Z; z++) s += pred[(size_t)z*MDEC*NPADC + row];
    out[idx] = s;
}

static float* symaddr(const void* sym){
    void* p = nullptr;
    cudaGetSymbolAddress(&p, sym);
    return (float*)p;
}
static __nv_bfloat16* symaddr16(const void* sym){
    void* p = nullptr;
    cudaGetSymbolAddress(&p, sym);
    return (__nv_bfloat16*)p;
}

extern "C" void kernel_launch(void* const* d_in, const int* in_sizes, int n_in,
                              void* d_out, int out_size)
{
    const float* feat   = (const float*)d_in[0];
    const int*   label  = (const int*)  d_in[1];
    const float* vr     = (const float*)d_in[2];
    const float* e0_Wih = (const float*)d_in[3];
    const float* e0_Whh = (const float*)d_in[4];
    const float* e0_bih = (const float*)d_in[5];
    const float* e0_bhh = (const float*)d_in[6];
    const float* e1_Wih = (const float*)d_in[7];
    const float* e1_Whh = (const float*)d_in[8];
    const float* e1_bih = (const float*)d_in[9];
    const float* e1_bhh = (const float*)d_in[10];
    const float* enc_W  = (const float*)d_in[11];
    const float* enc_b  = (const float*)d_in[12];
    const float* q_W    = (const float*)d_in[13];
    const float* q_b    = (const float*)d_in[14];
    const float* k_W    = (const float*)d_in[15];
    const float* k_b    = (const float*)d_in[16];
    const float* s_W    = (const float*)d_in[17];
    const float* s_b    = (const float*)d_in[18];
    const float* emb    = (const float*)d_in[19];
    const float* d0_Wih = (const float*)d_in[20];
    const float* d0_Whh = (const float*)d_in[21];
    const float* d0_bih = (const float*)d_in[22];
    const float* d0_bhh = (const float*)d_in[23];
    const float* d1_Wih = (const float*)d_in[24];
    const float* d1_Whh = (const float*)d_in[25];
    const float* d1_bih = (const float*)d_in[26];
    const float* d1_bhh = (const float*)d_in[27];
    const float* pred_W = (const float*)d_in[28];
    const float* pred_b = (const float*)d_in[29];
    float* out = (float*)d_out;

    float* gbuf  = symaddr(g_gbuf);
    float* seqa  = symaddr(g_seqa);
    float* seqb  = symaddr(g_seqb);
    float* hid   = symaddr(g_hid);
    float* hol   = symaddr(g_hol);
    float* qbuf  = symaddr(g_q);
    float* kc    = symaddr(g_kc);
    float* pred  = symaddr(g_pred);
    float* score = symaddr(g_score);
    __nv_bfloat16* padhi = symaddr16(g_padhi);
    __nv_bfloat16* padlo = symaddr16(g_padlo);
    __nv_bfloat16* kwhi  = symaddr16(g_kwhi);
    __nv_bfloat16* kwlo  = symaddr16(g_kwlo);
    __nv_bfloat16* wihhi = symaddr16(g_wihhi);
    __nv_bfloat16* wihlo = symaddr16(g_wihlo);
    __nv_bfloat16* acthi = symaddr16(g_acthi);
    __nv_bfloat16* actlo = symaddr16(g_actlo);
    __nv_bfloat16* qwhi  = symaddr16(g_qwhi);
    __nv_bfloat16* qwlo  = symaddr16(g_qwlo);
    __nv_bfloat16* pwhi  = symaddr16(g_pwhi);
    __nv_bfloat16* pwlo  = symaddr16(g_pwlo);
    __nv_bfloat16* cathi = symaddr16(g_cathi);
    __nv_bfloat16* catlo = symaddr16(g_catlo);

    const int lstm_smem = (16*516 + 32*516 + 16*33 + 128) * 4;
    cudaFuncSetAttribute(lstm_layer, cudaFuncAttributeMaxDynamicSharedMemorySize, lstm_smem);
    const int score_smem = (27*512 + 512 + 512) * 4;
    cudaFuncSetAttribute(score_kernel, cudaFuncAttributeMaxDynamicSharedMemorySize, score_smem);
    const int af_smem = (TDEC*NPIX + 64*241) * 4;
    cudaFuncSetAttribute(attnfeat_kernel, cudaFuncAttributeMaxDynamicSharedMemorySize, af_smem);
    const int hol_smem = (32*513 + 4*512 + 256) * 4;
    cudaFuncSetAttribute(holistic_kernel, cudaFuncAttributeMaxDynamicSharedMemorySize, hol_smem);
    const int mma_smem = 2*STAGE_BYTES;
    cudaFuncSetAttribute(mma_gemm, cudaFuncAttributeMaxDynamicSharedMemorySize, mma_smem);
    const int w_smem = 2*WSTAGE_BYTES;
    cudaFuncSetAttribute(conv_gemm2, cudaFuncAttributeMaxDynamicSharedMemorySize, CONV_SMEM);
    cudaFuncSetAttribute(gemm_w, cudaFuncAttributeMaxDynamicSharedMemorySize, w_smem);
    const size_t WSZ = (size_t)2048*NCH;

    static cudaStream_t s2 = nullptr;
    static cudaEvent_t eFork = nullptr, eJoin = nullptr;
    if (!s2) {
        cudaStreamCreateWithFlags(&s2, cudaStreamNonBlocking);
        cudaEventCreateWithFlags(&eFork, cudaEventDisableTiming);
        cudaEventCreateWithFlags(&eJoin, cudaEventDisableTiming);
    }

    // ---- fork: conv path on s2; smem-padded to 1 CTA/SM so lstm co-resides ----
    cudaEventRecord(eFork, 0);
    cudaStreamWaitEvent(s2, eFork, 0);
    { dim3 g(4, NB*PADH); featpad_kernel<<<g, 256, 0, s2>>>(feat, padhi, padlo); }
    cvt_kw<<<(NCH*KCONV+255)/256, 256, 0, s2>>>(k_W, kwhi, kwlo);
    { dim3 g(4, 60); conv_gemm2<<<g, 256, CONV_SMEM, s2>>>(padhi, padlo, kwhi, kwlo, kc, k_b); }
    cudaEventRecord(eJoin, s2);

    // ---- main stream ----
    featv_kernel<<<(NB*NCH*WWW+255)/256, 256>>>(feat, acthi, actlo);
    { dim3 g((2048*NCH+255)/256, 4);
      cvt4<<<g, 256>>>(e0_Wih, e1_Wih, d0_Wih, d1_Wih, wihhi, wihlo); }
    cvt_split<<<(NCH*NCH+255)/256, 256>>>(q_W, qwhi, qwlo, NCH*NCH);
    cvt_split<<<(NCLASS*1536+255)/256, 256>>>(pred_W, pwhi, pwlo, NCLASS*1536);

    // encoder
    { dim3 g(16, 10); gemm_w<<<g, 256, w_smem>>>(acthi, actlo, wihhi, wihlo,
                                gbuf, MENC, 2048, NCH, e0_bih, e0_bhh); }
    lstm_layer<<<LSTM_BLOCKS, 256, lstm_smem>>>(gbuf, e0_Whh, seqa, TENC, acthi, actlo);
    { dim3 g(16, 10); gemm_w<<<g, 256, w_smem>>>(acthi, actlo, wihhi + WSZ, wihlo + WSZ,
                                gbuf, MENC, 2048, NCH, e1_bih, e1_bhh); }
    lstm_layer<<<LSTM_BLOCKS, 256, lstm_smem>>>(gbuf, e1_Whh, seqb, TENC, nullptr, nullptr);
    holistic_kernel<<<128, 256, hol_smem>>>(seqb + (size_t)(TENC-1)*NB*NCH, enc_W, enc_b, hol);

    // decoder
    tok_kernel<<<MDEC, 256>>>(hol, emb, label, acthi, actlo);
    { dim3 g(16, 7); gemm_w<<<g, 256, w_smem>>>(acthi, actlo, wihhi + 2*WSZ, wihlo + 2*WSZ,
                                gbuf, MDEC, 2048, NCH, d0_bih, d0_bhh); }
    lstm_layer<<<LSTM_BLOCKS, 256, lstm_smem>>>(gbuf, d0_Whh, seqa, TDEC, acthi, actlo);
    { dim3 g(16, 7); gemm_w<<<g, 256, w_smem>>>(acthi, actlo, wihhi + 3*WSZ, wihlo + 3*WSZ,
                                gbuf, MDEC, 2048, NCH, d1_bih, d1_bhh); }
    lstm_layer<<<LSTM_BLOCKS, 256, lstm_smem>>>(gbuf, d1_Whh, hid, TDEC, acthi, actlo);

    // attention (join conv before score)
    { dim3 g(8, 7, 1); mma_gemm<<<g, 256, mma_smem>>>(acthi, actlo, qwhi, qwlo,
                                qbuf, MDEC, NCH, NCH, NCH, q_b, nullptr); }
    cudaStreamWaitEvent(0, eJoin, 0);
    { dim3 g(20, 32); score_kernel<<<g, 256, score_smem>>>(kc, qbuf, s_W, s_b, score); }
    softmax_kernel<<<NB, 256>>>(score, hid, hol, vr, cathi, catlo);
    { dim3 g(8, 32); attnfeat_kernel<<<g, 256, af_smem>>>(score, feat, cathi, catlo); }

    // prediction
    { dim3 g(2, 7, PRED_Z); mma_gemm<<<g, 256, mma_smem>>>(cathi, catlo, pwhi, pwlo,
                                pred, MDEC, NPADC, 1536, NCLASS, pred_b, nullptr); }
    out_kernel<<<(NB*LLAB*NCLASS+255)/256, 256>>>(pred, out);
}

// round 16
// speedup vs baseline: 1.1363x; 1.1363x over previous
#include <cuda_runtime.h>
#include <cuda_bf16.h>
#include <math.h>
#include <stdint.h>

#define NB 32
#define NCH 512
#define HHH 6
#define WWW 40
#define NPIX 240
#define NCLASS 97
#define NPADC 128
#define TENC 40
#define TDEC 27
#define LLAB 26
#define MENC 1280
#define MDEC 864
#define KCONV 4608
#define MCONV 7680
#define LSTM_BLOCKS 128
#define PRED_Z 4
#define PADW 42
#define PADH 8

__device__ float g_gbuf[MENC*2048];
__device__ float g_seqa[MENC*NCH];
__device__ float g_seqb[MENC*NCH];
__device__ float g_hid[MDEC*NCH];
__device__ float g_hol[NB*NCH];
__device__ float g_q[MDEC*NCH];
__device__ float g_kc[MCONV*NCH];
__device__ float g_pred[PRED_Z*MDEC*NPADC];
__device__ float g_score[NB*TDEC*NPIX];
__device__ __nv_bfloat16 g_padhi[NB*PADH*PADW*NCH];
__device__ __nv_bfloat16 g_padlo[NB*PADH*PADW*NCH];
__device__ __nv_bfloat16 g_kwhi[NCH*KCONV];
__device__ __nv_bfloat16 g_kwlo[NCH*KCONV];
__device__ __nv_bfloat16 g_wihhi[4*2048*NCH];
__device__ __nv_bfloat16 g_wihlo[4*2048*NCH];
__device__ __nv_bfloat16 g_acthi[MENC*NCH];
__device__ __nv_bfloat16 g_actlo[MENC*NCH];
__device__ __nv_bfloat16 g_qwhi[NCH*NCH];
__device__ __nv_bfloat16 g_qwlo[NCH*NCH];
__device__ __nv_bfloat16 g_pwhi[NCLASS*1536];
__device__ __nv_bfloat16 g_pwlo[NCLASS*1536];
__device__ __nv_bfloat16 g_cathi[MDEC*1536];
__device__ __nv_bfloat16 g_catlo[MDEC*1536];
__device__ unsigned g_cnt = 0;
__device__ unsigned g_gen = 0;

// ------------- helpers -------------
__device__ __forceinline__ float mufu_tanh(float x){
    float y; asm("tanh.approx.f32 %0, %1;" : "=f"(y) : "f"(x)); return y;
}
__device__ __forceinline__ float sigm(float x){ return 1.f/(1.f + expf(-x)); }
__device__ __forceinline__ void split2(float v, __nv_bfloat16& h, __nv_bfloat16& l){
    h = __float2bfloat16(v);
    l = __float2bfloat16(v - __bfloat162float(h));
}
__device__ __forceinline__ float psum2(unsigned long long v){
    return __uint_as_float((uint32_t)v) + __uint_as_float((uint32_t)(v >> 32));
}

#define MMA_B16(c, a, b0, b1) asm volatile( \
  "mma.sync.aligned.m16n8k16.row.col.f32.bf16.bf16.f32 " \
  "{%0,%1,%2,%3},{%4,%5,%6,%7},{%8,%9},{%0,%1,%2,%3};\n" \
  : "+f"((c)[0]),"+f"((c)[1]),"+f"((c)[2]),"+f"((c)[3]) \
  : "r"((a)[0]),"r"((a)[1]),"r"((a)[2]),"r"((a)[3]),"r"(b0),"r"(b1))

#define LDSM4(r, addr) asm volatile( \
  "ldmatrix.sync.aligned.m8n8.x4.shared.b16 {%0,%1,%2,%3}, [%4];" \
  : "=r"((r)[0]),"=r"((r)[1]),"=r"((r)[2]),"=r"((r)[3]) : "r"(addr))

#define FMA2(c, a, b) asm("fma.rn.f32x2 %0, %1, %2, %0;" : "+l"(c) : "l"(a), "l"(b))

__device__ __forceinline__ void cp16(uint32_t daddr, const void* src, int srcsz){
    asm volatile("cp.async.cg.shared.global [%0], [%1], 16, %2;\n"
                 :: "r"(daddr), "l"(src), "r"(srcsz));
}

__global__ void cvt4(const float* __restrict__ a0, const float* __restrict__ a1,
                     const float* __restrict__ a2, const float* __restrict__ a3,
                     __nv_bfloat16* __restrict__ hi, __nv_bfloat16* __restrict__ lo){
    int which = blockIdx.y;
    const float* src = which == 0 ? a0 : which == 1 ? a1 : which == 2 ? a2 : a3;
    int i = blockIdx.x*256 + threadIdx.x;
    if (i < 2048*NCH) {
        size_t o = (size_t)which*2048*NCH + i;
        split2(src[i], hi[o], lo[o]);
    }
}
// q + pred weight splits in one launch
__global__ void cvt2(const float* __restrict__ qW, const float* __restrict__ pW,
                     __nv_bfloat16* __restrict__ qhi, __nv_bfloat16* __restrict__ qlo,
                     __nv_bfloat16* __restrict__ phi, __nv_bfloat16* __restrict__ plo){
    int i = blockIdx.x*256 + threadIdx.x;
    if (blockIdx.y == 0) {
        if (i < NCH*NCH) split2(qW[i], qhi[i], qlo[i]);
    } else {
        if (i < NCLASS*1536) split2(pW[i], phi[i], plo[i]);
    }
}
__global__ void cvt_kw(const float* __restrict__ kW, __nv_bfloat16* __restrict__ hi,
                       __nv_bfloat16* __restrict__ lo){
    int i = blockIdx.x*256 + threadIdx.x;
    if (i >= NCH*KCONV) return;
    int o = i / KCONV, r = i - o*KCONV;
    int tap = r >> 9, cin = r & 511;
    split2(kW[(size_t)o*KCONV + cin*9 + tap], hi[i], lo[i]);
}
__global__ void featv_kernel(const float* __restrict__ feat,
                             __nv_bfloat16* __restrict__ hi, __nv_bfloat16* __restrict__ lo){
    int idx = blockIdx.x*256 + threadIdx.x;
    if (idx >= NB*NCH*WWW) return;
    int w = idx % WWW;
    int c = (idx / WWW) % NCH;
    int b = idx / (WWW*NCH);
    const float* p = feat + ((size_t)(b*NCH + c)*HHH)*WWW + w;
    float m = p[0];
    #pragma unroll
    for (int h = 1; h < HHH; h++) m = fmaxf(m, p[h*WWW]);
    size_t o = ((size_t)(w*NB + b))*NCH + c;
    split2(m, hi[o], lo[o]);
}

__global__ __launch_bounds__(256) void featpad_kernel(
    const float* __restrict__ feat,
    __nv_bfloat16* __restrict__ hi, __nv_bfloat16* __restrict__ lo)
{
    __shared__ float sm[128*41];
    const int tid = threadIdx.x;
    const int c0 = blockIdx.x * 128;
    const int b  = blockIdx.y >> 3;
    const int yy = blockIdx.y & 7;
    const int y  = yy - 1;
    const bool rowvalid = (y >= 0 && y < HHH);
    if (rowvalid) {
        for (int i = tid; i < 128*WWW; i += 256) {
            int c = i / WWW, x = i - c*WWW;
            sm[c*41 + x] = feat[((size_t)(b*NCH + c0 + c)*HHH + y)*WWW + x];
        }
    }
    __syncthreads();
    for (int i = tid; i < PADW*128; i += 256) {
        int xx = i >> 7, c = i & 127;
        int x = xx - 1;
        float v = (rowvalid && x >= 0 && x < WWW) ? sm[c*41 + x] : 0.f;
        size_t o = ((size_t)((b*PADH + yy)*PADW + xx))*NCH + c0 + c;
        split2(v, hi[o], lo[o]);
    }
}

// ---- tile geometry ----
#define SA_ELEM (128*40)
#define SB_ELEM (64*40)
#define STG_AH 0
#define STG_AL (SA_ELEM*2)
#define STG_BH (2*SA_ELEM*2)
#define STG_BL (2*SA_ELEM*2 + SB_ELEM*2)
#define STAGE_BYTES (2*SA_ELEM*2 + 2*SB_ELEM*2)
#define W_AH 0
#define W_AL (SA_ELEM*2)
#define W_BH (2*SA_ELEM*2)
#define W_BL (3*SA_ELEM*2)
#define WSTAGE_BYTES (4*SA_ELEM*2)

// implicit-conv GEMM: 128x128 tile, 2 CTA/SM. grid (4, 60).
__global__ __launch_bounds__(256, 2) void conv_gemm2(
    const __nv_bfloat16* __restrict__ Ahi, const __nv_bfloat16* __restrict__ Alo,
    const __nv_bfloat16* __restrict__ Bhi, const __nv_bfloat16* __restrict__ Blo,
    float* __restrict__ C, const float* __restrict__ bias)
{
    extern __shared__ __nv_bfloat16 smb[];
    const int tid = threadIdx.x;
    const int lane = tid & 31, warp = tid >> 5;
    const int wm = (warp & 3) << 5;
    const int wn = (warp >> 2) << 6;
    const int m0 = blockIdx.y * 128, n0 = blockIdx.x * 128;
    float acc[2][8][4];
    #pragma unroll
    for (int a = 0; a < 2; a++)
        #pragma unroll
        for (int b = 0; b < 8; b++)
            #pragma unroll
            for (int c = 0; c < 4; c++) acc[a][b][c] = 0.f;

    const uint32_t smemBase = (uint32_t)__cvta_generic_to_shared(smb);
    const int r0 = tid >> 2,          s0 = tid & 3;
    const int r1 = (tid + 256) >> 2,  s1 = (tid + 256) & 3;
    int gm0 = m0 + r0, gm1 = m0 + r1;
    int b0i = gm0 / NPIX, p0i = gm0 - b0i*NPIX, y0 = p0i / WWW, x0 = p0i - y0*WWW;
    int b1i = gm1 / NPIX, p1i = gm1 - b1i*NPIX, y1 = p1i / WWW, x1 = p1i - y1*WWW;
    const int pb0 = (b0i*PADH + y0)*PADW + x0;
    const int pb1 = (b1i*PADH + y1)*PADW + x1;
    const size_t rB0 = (size_t)(n0 + r0)*KCONV;
    const size_t rB1 = (size_t)(n0 + r1)*KCONV;
    const uint32_t d0 = (uint32_t)(r0*40 + s0*8)*2;
    const uint32_t d1 = (uint32_t)(r1*40 + s1*8)*2;
    const int o0 = s0*8, o1 = s1*8;

    const uint32_t aOff = (uint32_t)((wm + (lane & 15))*40 + (lane >> 4)*8)*2;
    const uint32_t bOff = (uint32_t)((wn + (lane & 7) + ((lane >> 4) & 1)*8)*40
                                     + ((lane >> 3) & 1)*8)*2;
    const int KT = KCONV >> 5;

    auto loadStage = [&](int it){
        int k0 = it << 5;
        uint32_t sb = smemBase + (it & 1) * WSTAGE_BYTES;
        int k0a = k0 + o0, k1a = k0 + o1;
        int tap0 = k0a >> 9, cin0 = k0a & 511;
        int tap1 = k1a >> 9, cin1 = k1a & 511;
        int td0 = (tap0*11) >> 5, td1 = (tap1*11) >> 5;
        int tofs0 = td0*PADW + (tap0 - td0*3);
        int tofs1 = td1*PADW + (tap1 - td1*3);
        size_t a0 = (size_t)(pb0 + tofs0)*NCH + cin0;
        size_t a1 = (size_t)(pb1 + tofs1)*NCH + cin1;
        cp16(sb + W_AH + d0, Ahi + a0, 16);
        cp16(sb + W_AH + d1, Ahi + a1, 16);
        cp16(sb + W_AL + d0, Alo + a0, 16);
        cp16(sb + W_AL + d1, Alo + a1, 16);
        cp16(sb + W_BH + d0, Bhi + rB0 + k0 + o0, 16);
        cp16(sb + W_BH + d1, Bhi + rB1 + k0 + o1, 16);
        cp16(sb + W_BL + d0, Blo + rB0 + k0 + o0, 16);
        cp16(sb + W_BL + d1, Blo + rB1 + k0 + o1, 16);
        asm volatile("cp.async.commit_group;\n");
    };

    loadStage(0);
    for (int it = 0; it < KT; it++) {
        if (it + 1 < KT) {
            loadStage(it + 1);
            asm volatile("cp.async.wait_group 1;\n");
        } else {
            asm volatile("cp.async.wait_group 0;\n");
        }
        __syncthreads();
        uint32_t sb = smemBase + (it & 1) * WSTAGE_BYTES;
        #pragma unroll
        for (int s = 0; s < 2; s++) {
            const uint32_t kB = s*32;
            uint32_t ah[2][4], al[2][4];
            LDSM4(ah[0], sb + W_AH + aOff + kB);
            LDSM4(ah[1], sb + W_AH + aOff + 16*80 + kB);
            LDSM4(al[0], sb + W_AL + aOff + kB);
            LDSM4(al[1], sb + W_AL + aOff + 16*80 + kB);
            #pragma unroll
            for (int ntp = 0; ntp < 4; ntp++) {
                uint32_t bh[4], bl[4];
                LDSM4(bh, sb + W_BH + bOff + ntp*16*80 + kB);
                LDSM4(bl, sb + W_BL + bOff + ntp*16*80 + kB);
                #pragma unroll
                for (int mt = 0; mt < 2; mt++) {
                    MMA_B16(acc[mt][2*ntp],   ah[mt], bh[0], bh[1]);
                    MMA_B16(acc[mt][2*ntp],   ah[mt], bl[0], bl[1]);
                    MMA_B16(acc[mt][2*ntp],   al[mt], bh[0], bh[1]);
                    MMA_B16(acc[mt][2*ntp+1], ah[mt], bh[2], bh[3]);
                    MMA_B16(acc[mt][2*ntp+1], ah[mt], bl[2], bl[3]);
                    MMA_B16(acc[mt][2*ntp+1], al[mt], bh[2], bh[3]);
                }
            }
        }
        __syncthreads();
    }
    const int r = lane >> 2, kq = (lane & 3) << 1;
    #pragma unroll
    for (int mt = 0; mt < 2; mt++) {
        #pragma unroll
        for (int nt = 0; nt < 8; nt++) {
            int m = m0 + wm + mt*16 + r;
            int n = n0 + wn + nt*8 + kq;
            float bv0 = bias[n], bv1 = bias[n+1];
            C[(size_t)m*NCH + n]       = acc[mt][nt][0] + bv0;
            C[(size_t)m*NCH + n + 1]   = acc[mt][nt][1] + bv1;
            C[(size_t)(m+8)*NCH + n]   = acc[mt][nt][2] + bv0;
            C[(size_t)(m+8)*NCH + n+1] = acc[mt][nt][3] + bv1;
        }
    }
}

// generic 128x128 GEMM (xW)
__global__ __launch_bounds__(256, 2) void gemm_w(
    const __nv_bfloat16* __restrict__ Ahi, const __nv_bfloat16* __restrict__ Alo,
    const __nv_bfloat16* __restrict__ Bhi, const __nv_bfloat16* __restrict__ Blo,
    float* __restrict__ C, int M, int N, int K,
    const float* __restrict__ bias1, const float* __restrict__ bias2)
{
    extern __shared__ __nv_bfloat16 smb[];
    const int tid = threadIdx.x;
    const int lane = tid & 31, warp = tid >> 5;
    const int wm = (warp & 3) << 5;
    const int wn = (warp >> 2) << 6;
    const int m0 = blockIdx.y * 128, n0 = blockIdx.x * 128;
    float acc[2][8][4];
    #pragma unroll
    for (int a = 0; a < 2; a++)
        #pragma unroll
        for (int b = 0; b < 8; b++)
            #pragma unroll
            for (int c = 0; c < 4; c++) acc[a][b][c] = 0.f;

    const uint32_t smemBase = (uint32_t)__cvta_generic_to_shared(smb);
    const int r0 = tid >> 2,          s0 = tid & 3;
    const int r1 = (tid + 256) >> 2,  s1 = (tid + 256) & 3;
    const int gm0 = m0 + r0, gm1 = m0 + r1;
    const int szA0 = (gm0 < M) ? 16 : 0;
    const int szA1 = (gm1 < M) ? 16 : 0;
    const size_t rA0 = (size_t)min(gm0, M-1)*K, rA1 = (size_t)min(gm1, M-1)*K;
    const size_t rB0 = (size_t)(n0 + r0)*K, rB1 = (size_t)(n0 + r1)*K;
    const uint32_t d0 = (uint32_t)(r0*40 + s0*8)*2;
    const uint32_t d1 = (uint32_t)(r1*40 + s1*8)*2;
    const int o0 = s0*8, o1 = s1*8;
    const uint32_t aOff = (uint32_t)((wm + (lane & 15))*40 + (lane >> 4)*8)*2;
    const uint32_t bOff = (uint32_t)((wn + (lane & 7) + ((lane >> 4) & 1)*8)*40
                                     + ((lane >> 3) & 1)*8)*2;
    const int KT = K >> 5;

    auto loadStage = [&](int it){
        int k0 = it << 5;
        uint32_t sb = smemBase + (it & 1) * WSTAGE_BYTES;
        cp16(sb + W_AH + d0, Ahi + rA0 + k0 + o0, szA0);
        cp16(sb + W_AH + d1, Ahi + rA1 + k0 + o1, szA1);
        cp16(sb + W_AL + d0, Alo + rA0 + k0 + o0, szA0);
        cp16(sb + W_AL + d1, Alo + rA1 + k0 + o1, szA1);
        cp16(sb + W_BH + d0, Bhi + rB0 + k0 + o0, 16);
        cp16(sb + W_BH + d1, Bhi + rB1 + k0 + o1, 16);
        cp16(sb + W_BL + d0, Blo + rB0 + k0 + o0, 16);
        cp16(sb + W_BL + d1, Blo + rB1 + k0 + o1, 16);
        asm volatile("cp.async.commit_group;\n");
    };

    loadStage(0);
    for (int it = 0; it < KT; it++) {
        if (it + 1 < KT) {
            loadStage(it + 1);
            asm volatile("cp.async.wait_group 1;\n");
        } else {
            asm volatile("cp.async.wait_group 0;\n");
        }
        __syncthreads();
        uint32_t sb = smemBase + (it & 1) * WSTAGE_BYTES;
        #pragma unroll
        for (int s = 0; s < 2; s++) {
            const uint32_t kB = s*32;
            uint32_t ah[2][4], al[2][4];
            LDSM4(ah[0], sb + W_AH + aOff + kB);
            LDSM4(ah[1], sb + W_AH + aOff + 16*80 + kB);
            LDSM4(al[0], sb + W_AL + aOff + kB);
            LDSM4(al[1], sb + W_AL + aOff + 16*80 + kB);
            #pragma unroll
            for (int ntp = 0; ntp < 4; ntp++) {
                uint32_t bh[4], bl[4];
                LDSM4(bh, sb + W_BH + bOff + ntp*16*80 + kB);
                LDSM4(bl, sb + W_BL + bOff + ntp*16*80 + kB);
                #pragma unroll
                for (int mt = 0; mt < 2; mt++) {
                    MMA_B16(acc[mt][2*ntp],   ah[mt], bh[0], bh[1]);
                    MMA_B16(acc[mt][2*ntp],   ah[mt], bl[0], bl[1]);
                    MMA_B16(acc[mt][2*ntp],   al[mt], bh[0], bh[1]);
                    MMA_B16(acc[mt][2*ntp+1], ah[mt], bh[2], bh[3]);
                    MMA_B16(acc[mt][2*ntp+1], ah[mt], bl[2], bl[3]);
                    MMA_B16(acc[mt][2*ntp+1], al[mt], bh[2], bh[3]);
                }
            }
        }
        __syncthreads();
    }
    const int r = lane >> 2, kq = (lane & 3) << 1;
    #pragma unroll
    for (int mt = 0; mt < 2; mt++) {
        #pragma unroll
        for (int nt = 0; nt < 8; nt++) {
            int m = m0 + wm + mt*16 + r;
            int n = n0 + wn + nt*8 + kq;
            float bv0 = 0.f, bv1 = 0.f;
            if (bias1) { bv0 += bias1[n]; bv1 += bias1[n+1]; }
            if (bias2) { bv0 += bias2[n]; bv1 += bias2[n+1]; }
            if (m < M) {
                C[(size_t)m*N + n]     = acc[mt][nt][0] + bv0;
                C[(size_t)m*N + n + 1] = acc[mt][nt][1] + bv1;
            }
            if (m + 8 < M) {
                C[(size_t)(m+8)*N + n]     = acc[mt][nt][2] + bv0;
                C[(size_t)(m+8)*N + n + 1] = acc[mt][nt][3] + bv1;
            }
        }
    }
}

// 128x64 GEMM (q, pred). B-row guard + split-K via gridDim.z.
__global__ __launch_bounds__(256) void mma_gemm(
    const __nv_bfloat16* __restrict__ Ahi, const __nv_bfloat16* __restrict__ Alo,
    const __nv_bfloat16* __restrict__ Bhi, const __nv_bfloat16* __restrict__ Blo,
    float* __restrict__ C, int M, int N, int K, int NBrows,
    const float* __restrict__ bias1, const float* __restrict__ bias2)
{
    extern __shared__ __nv_bfloat16 smb[];
    const int tid = threadIdx.x;
    const int lane = tid & 31, warp = tid >> 5;
    const int wm = (warp & 3) << 5;
    const int wn = (warp >> 2) << 5;
    const int m0 = blockIdx.y * 128, n0 = blockIdx.x * 64;
    const int Kc = K / gridDim.z;
    const int kbeg = blockIdx.z * Kc;
    float acc[2][4][4];
    #pragma unroll
    for (int a = 0; a < 2; a++)
        #pragma unroll
        for (int b = 0; b < 4; b++)
            #pragma unroll
            for (int c = 0; c < 4; c++) acc[a][b][c] = 0.f;

    const uint32_t smemBase = (uint32_t)__cvta_generic_to_shared(smb);
    const int ar0 = tid >> 2,         as0 = tid & 3;
    const int ar1 = (tid + 256) >> 2, as1 = (tid + 256) & 3;
    const int br  = tid >> 2,         bs  = tid & 3;
    const int gm0 = m0 + ar0, gm1 = m0 + ar1, gn = n0 + br;
    const int szA0 = (gm0 < M) ? 16 : 0;
    const int szA1 = (gm1 < M) ? 16 : 0;
    const int szB  = (gn < NBrows) ? 16 : 0;
    const size_t rA0 = (size_t)min(gm0, M-1)*K, rA1 = (size_t)min(gm1, M-1)*K;
    const size_t rB  = (size_t)min(gn, NBrows-1)*K;
    const uint32_t dA0 = (uint32_t)(ar0*40 + as0*8)*2;
    const uint32_t dA1 = (uint32_t)(ar1*40 + as1*8)*2;
    const uint32_t dB  = (uint32_t)(br*40 + bs*8)*2;
    const int oA0 = as0*8, oA1 = as1*8, oB = bs*8;
    const uint32_t aOff = (uint32_t)((wm + (lane & 15))*40 + (lane >> 4)*8)*2;
    const uint32_t bOff = (uint32_t)((wn + (lane & 7) + ((lane >> 4) & 1)*8)*40
                                     + ((lane >> 3) & 1)*8)*2;
    const int KT = Kc >> 5;
    {
        uint32_t sb = smemBase;
        cp16(sb + STG_AH + dA0, Ahi + rA0 + kbeg + oA0, szA0);
        cp16(sb + STG_AH + dA1, Ahi + rA1 + kbeg + oA1, szA1);
        cp16(sb + STG_AL + dA0, Alo + rA0 + kbeg + oA0, szA0);
        cp16(sb + STG_AL + dA1, Alo + rA1 + kbeg + oA1, szA1);
        cp16(sb + STG_BH + dB,  Bhi + rB  + kbeg + oB,  szB);
        cp16(sb + STG_BL + dB,  Blo + rB  + kbeg + oB,  szB);
        asm volatile("cp.async.commit_group;\n");
    }
    for (int it = 0; it < KT; it++) {
        if (it + 1 < KT) {
            int k0 = kbeg + ((it + 1) << 5);
            uint32_t sb = smemBase + ((it + 1) & 1) * STAGE_BYTES;
            cp16(sb + STG_AH + dA0, Ahi + rA0 + k0 + oA0, szA0);
            cp16(sb + STG_AH + dA1, Ahi + rA1 + k0 + oA1, szA1);
            cp16(sb + STG_AL + dA0, Alo + rA0 + k0 + oA0, szA0);
            cp16(sb + STG_AL + dA1, Alo + rA1 + k0 + oA1, szA1);
            cp16(sb + STG_BH + dB,  Bhi + rB  + k0 + oB,  szB);
            cp16(sb + STG_BL + dB,  Blo + rB  + k0 + oB,  szB);
            asm volatile("cp.async.commit_group;\n");
            asm volatile("cp.async.wait_group 1;\n");
        } else {
            asm volatile("cp.async.wait_group 0;\n");
        }
        __syncthreads();
        uint32_t sb = smemBase + (it & 1) * STAGE_BYTES;
        #pragma unroll
        for (int s = 0; s < 2; s++) {
            const uint32_t kB = s*32;
            uint32_t ah[2][4], al[2][4];
            LDSM4(ah[0], sb + STG_AH + aOff + kB);
            LDSM4(ah[1], sb + STG_AH + aOff + 16*80 + kB);
            LDSM4(al[0], sb + STG_AL + aOff + kB);
            LDSM4(al[1], sb + STG_AL + aOff + 16*80 + kB);
            #pragma unroll
            for (int ntp = 0; ntp < 2; ntp++) {
                uint32_t bh[4], bl[4];
                LDSM4(bh, sb + STG_BH + bOff + ntp*16*80 + kB);
                LDSM4(bl, sb + STG_BL + bOff + ntp*16*80 + kB);
                #pragma unroll
                for (int mt = 0; mt < 2; mt++) {
                    MMA_B16(acc[mt][2*ntp],   ah[mt], bh[0], bh[1]);
                    MMA_B16(acc[mt][2*ntp],   ah[mt], bl[0], bl[1]);
                    MMA_B16(acc[mt][2*ntp],   al[mt], bh[0], bh[1]);
                    MMA_B16(acc[mt][2*ntp+1], ah[mt], bh[2], bh[3]);
                    MMA_B16(acc[mt][2*ntp+1], ah[mt], bl[2], bl[3]);
                    MMA_B16(acc[mt][2*ntp+1], al[mt], bh[2], bh[3]);
                }
            }
        }
        __syncthreads();
    }
    float* Co = C + (size_t)blockIdx.z * M * N;
    const bool addb = (blockIdx.z == 0);
    const int r = lane >> 2, kq = (lane & 3) << 1;
    #pragma unroll
    for (int mt = 0; mt < 2; mt++) {
        #pragma unroll
        for (int nt = 0; nt < 4; nt++) {
            int m = m0 + wm + mt*16 + r;
            int n = n0 + wn + nt*8 + kq;
            float bv0 = 0.f, bv1 = 0.f;
            if (addb && bias1) {
                if (n < NBrows)     bv0 += bias1[n];
                if (n + 1 < NBrows) bv1 += bias1[n+1];
            }
            if (addb && bias2) {
                if (n < NBrows)     bv0 += bias2[n];
                if (n + 1 < NBrows) bv1 += bias2[n+1];
            }
            if (m < M) {
                Co[(size_t)m*N + n]     = acc[mt][nt][0] + bv0;
                Co[(size_t)m*N + n + 1] = acc[mt][nt][1] + bv1;
            }
            if (m + 8 < M) {
                Co[(size_t)(m+8)*N + n]     = acc[mt][nt][2] + bv0;
                Co[(size_t)(m+8)*N + n + 1] = acc[mt][nt][3] + bv1;
            }
        }
    }
}

__global__ __launch_bounds__(256) void holistic_kernel(
    const float* __restrict__ A, const float* __restrict__ W,
    const float* __restrict__ bias, float* __restrict__ C)
{
    extern __shared__ float sm[];
    float* sA = sm;
    float* sW = sm + 32*513;
    float* sP = sW + 4*512;
    const int tid = threadIdx.x;
    const int j0 = blockIdx.x * 4;
    for (int i = tid; i < 32*512; i += 256)
        sA[(i>>9)*513 + (i&511)] = A[i];
    for (int i = tid; i < 4*512; i += 256)
        sW[i] = W[(size_t)(j0 + (i>>9))*512 + (i&511)];
    __syncthreads();
    const int bb = tid & 31, jq = (tid>>5)&3, kh = tid>>7;
    const float* ar = sA + bb*513 + kh*256;
    const float* wr = sW + jq*512 + kh*256;
    float acc = 0.f;
    #pragma unroll 8
    for (int k = 0; k < 256; k++) acc = fmaf(ar[k], wr[k], acc);
    sP[tid] = acc;
    __syncthreads();
    if (kh == 0) C[bb*512 + j0 + jq] = sP[tid] + sP[tid+128] + bias[j0+jq];
}

// persistent LSTM layer: 4 batches/thread, split-K halves (reduced crossbar phases)
__global__ __launch_bounds__(256) void lstm_layer(
    const float* __restrict__ gpre, const float* __restrict__ Whh,
    float* __restrict__ seq, int T,
    __nv_bfloat16* __restrict__ ohi, __nv_bfloat16* __restrict__ olo)
{
    extern __shared__ float sm[];
    float* sW  = sm;                       // [16][516]
    float* sh  = sm + 16*516;              // [32][516]
    float* gex = sm + 16*516 + 32*516;     // [2][16][33]
    float* sc  = gex + 2*528;              // [128]
    const int tid = threadIdx.x;
    const int j0 = blockIdx.x * 4;
    #pragma unroll
    for (int rr = 0; rr < 16; rr++) {
        int grow = (rr & 3)*512 + j0 + (rr >> 2);
        for (int k = tid*4; k < 512; k += 1024) {
            float4 v = *(const float4*)(Whh + (size_t)grow*512 + k);
            *(float4*)&sW[rr*516 + k] = v;
        }
    }
    if (tid < 128) sc[tid] = 0.f;
    __syncthreads();
    const int half = tid >> 7;            // k-half
    const int t2   = tid & 127;
    const int row  = t2 & 15;             // gate-row 0..15
    const int bg   = t2 >> 4;             // batch group 0..7 (4 batches each)
    const int kb   = half << 8;           // 0 or 256
    const int cu   = tid & 3, cb = tid >> 2;
    const int cj   = j0 + cu;
    for (int t = 0; t < T; t++) {
        float gpi = 0.f, gpf = 0.f, gpg = 0.f, gpo = 0.f;
        if (tid < 128) {
            const float* gp = gpre + ((size_t)t*NB + cb)*2048;
            gpi = gp[cj]; gpf = gp[512 + cj]; gpg = gp[1024 + cj]; gpo = gp[1536 + cj];
        }
        if (t > 0) {
            const float* hp = seq + (size_t)(t-1)*NB*NCH;
            #pragma unroll
            for (int j = 0; j < 16; j++) {
                int v = tid + j*256;
                int bb = v >> 7, k4 = (v & 127) << 2;
                float4 x = __ldcg((const float4*)(hp + bb*512 + k4));
                *(float4*)&sh[bb*516 + k4] = x;
            }
            __syncthreads();
            unsigned long long ax[4][2];
            #pragma unroll
            for (int j = 0; j < 4; j++) { ax[j][0] = 0ull; ax[j][1] = 0ull; }
            const float* wrow = sW + row*516 + kb;
            const float* hbase = sh + (bg*4)*516 + kb;
            #pragma unroll 4
            for (int i = 0; i < 64; i++) {
                int k = i*4;
                ulonglong2 w = *(const ulonglong2*)(wrow + k);
                #pragma unroll
                for (int j = 0; j < 4; j++) {
                    ulonglong2 h = *(const ulonglong2*)(hbase + j*516 + k);
                    FMA2(ax[j][0], w.x, h.x);
                    FMA2(ax[j][1], w.y, h.y);
                }
            }
            #pragma unroll
            for (int j = 0; j < 4; j++)
                gex[half*528 + row*33 + bg*4 + j] = psum2(ax[j][0]) + psum2(ax[j][1]);
        } else {
            #pragma unroll
            for (int j = 0; j < 4; j++)
                gex[half*528 + row*33 + bg*4 + j] = 0.f;
        }
        __syncthreads();
        if (tid < 128) {
            int r0 = cu*4;
            float gi = gex[r0*33 + cb]     + gex[528 + r0*33 + cb]     + gpi;
            float gf = gex[(r0+1)*33 + cb] + gex[528 + (r0+1)*33 + cb] + gpf;
            float gg = gex[(r0+2)*33 + cb] + gex[528 + (r0+2)*33 + cb] + gpg;
            float go = gex[(r0+3)*33 + cb] + gex[528 + (r0+3)*33 + cb] + gpo;
            float c = sigm(gf)*sc[cu*32+cb] + sigm(gi)*tanhf(gg);
            sc[cu*32+cb] = c;
            float hv = sigm(go)*tanhf(c);
            size_t oo = (size_t)t*NB*NCH + cb*512 + cj;
            seq[oo] = hv;
            if (ohi) split2(hv, ohi[oo], olo[oo]);
        }
        if (t < T-1) {
            __syncthreads();
            if (tid == 0) {
                __threadfence();
                unsigned old = *((volatile unsigned*)&g_gen);
                __threadfence();
                unsigned n = atomicAdd(&g_cnt, 1u);
                if (n == LSTM_BLOCKS-1) {
                    g_cnt = 0;
                    __threadfence();
                    atomicAdd(&g_gen, 1u);
                } else {
                    while (*((volatile unsigned*)&g_gen) == old) { }
                }
            }
            __syncthreads();
        }
    }
}

__global__ void tok_kernel(const float* __restrict__ hol, const float* __restrict__ emb,
                           const int* __restrict__ label,
                           __nv_bfloat16* __restrict__ hi, __nv_bfloat16* __restrict__ lo){
    int row = blockIdx.x;
    int b = row & 31, t = row >> 5;
    const float* src = (t == 0) ? (hol + b*NCH)
                                : (emb + (size_t)label[b*LLAB + (t-1)]*NCH);
    for (int i = threadIdx.x; i < NCH; i += 256) {
        size_t o = (size_t)row*NCH + i;
        split2(src[i], hi[o], lo[o]);
    }
}

// scores: MUFU tanh
__global__ __launch_bounds__(256) void score_kernel(
    const float* __restrict__ kc, const float* __restrict__ qm,
    const float* __restrict__ sW, const float* __restrict__ sb,
    float* __restrict__ score)
{
    extern __shared__ float sm[];
    float* qs  = sm;
    float* sws = sm + 27*512;
    float* kcr = sws + 512;
    const int b  = blockIdx.y;
    const int p0 = blockIdx.x * 12;
    const int tid = threadIdx.x;
    const int lane = tid & 31, w = tid >> 5;
    for (int i = tid; i < 27*512; i += 256) {
        int t = i >> 9, c = i & 511;
        qs[i] = qm[((size_t)(t*32+b))*512 + c];
    }
    for (int i = tid; i < 512; i += 256) sws[i] = sW[i];
    __syncthreads();
    const float sbv = sb[0];
    for (int pp = 0; pp < 12; pp++) {
        int p = p0 + pp;
        for (int i = tid; i < 512; i += 256)
            kcr[i] = kc[((size_t)(b*NPIX + p))*512 + i];
        __syncthreads();
        for (int t = w; t < TDEC; t += 8) {
            float s = 0.f;
            const float* qrow = qs + t*512;
            #pragma unroll
            for (int i = 0; i < 16; i++) {
                int c = lane + i*32;
                s = fmaf(sws[c], mufu_tanh(kcr[c] + qrow[c]), s);
            }
            #pragma unroll
            for (int o = 16; o; o >>= 1) s += __shfl_xor_sync(0xffffffffu, s, o);
            if (lane == 0) score[((size_t)(b*TDEC) + t)*NPIX + p] = s + sbv;
        }
        __syncthreads();
    }
}

__global__ __launch_bounds__(256) void softmax_kernel(
    float* __restrict__ score, const float* __restrict__ hid,
    const float* __restrict__ hol, const float* __restrict__ vr,
    __nv_bfloat16* __restrict__ cathi, __nv_bfloat16* __restrict__ catlo)
{
    __shared__ float sc[TDEC*NPIX];
    const int b = blockIdx.x;
    const int tid = threadIdx.x;
    const int lane = tid & 31, w = tid >> 5;
    int vw = min(WWW, (int)ceilf(WWW * vr[b]));
    for (int i = tid; i < TDEC*NPIX; i += 256) {
        int p = i % NPIX;
        float v = score[(size_t)b*TDEC*NPIX + i];
        sc[i] = ((p % WWW) < vw) ? v : -1e30f;
    }
    __syncthreads();
    for (int t = w; t < TDEC; t += 8) {
        float m = -1e30f;
        for (int p = lane; p < NPIX; p += 32) m = fmaxf(m, sc[t*NPIX + p]);
        #pragma unroll
        for (int o = 16; o; o >>= 1) m = fmaxf(m, __shfl_xor_sync(0xffffffffu, m, o));
        float s = 0.f;
        for (int p = lane; p < NPIX; p += 32) {
            float e = __expf(sc[t*NPIX + p] - m);
            sc[t*NPIX + p] = e;
            s += e;
        }
        #pragma unroll
        for (int o = 16; o; o >>= 1) s += __shfl_xor_sync(0xffffffffu, s, o);
        float inv = 1.f / s;
        for (int p = lane; p < NPIX; p += 32)
            score[(size_t)b*TDEC*NPIX + t*NPIX + p] = sc[t*NPIX + p] * inv;
    }
    for (int i = tid; i < TDEC*512; i += 256) {
        int t = i >> 9, c = i & 511;
        size_t row = (size_t)(t*32 + b);
        split2(hid[row*512 + c], cathi[row*1536 + c], catlo[row*1536 + c]);
        split2(hol[b*512 + c], cathi[row*1536 + 1024 + c], catlo[row*1536 + 1024 + c]);
    }
}

__global__ __launch_bounds__(256) void attnfeat_kernel(
    const float* __restrict__ score, const float* __restrict__ feat,
    __nv_bfloat16* __restrict__ cathi, __nv_bfloat16* __restrict__ catlo)
{
    extern __shared__ float sm[];
    float* aw  = sm;
    float* fch = sm + TDEC*NPIX;
    const int b = blockIdx.y;
    const int c0 = blockIdx.x * 64;
    const int tid = threadIdx.x;
    for (int i = tid; i < TDEC*NPIX; i += 256)
        aw[i] = score[(size_t)b*TDEC*NPIX + i];
    for (int i = tid; i < 64*NPIX; i += 256) {
        int c = i / NPIX, p = i - c*NPIX;
        fch[c*241 + p] = feat[((size_t)(b*NCH + c0 + c))*NPIX + p];
    }
    __syncthreads();
    for (int task = tid; task < TDEC*64; task += 256) {
        int t = task >> 6, c = task & 63;
        float acc = 0.f;
        const float* ar = aw + t*NPIX;
        const float* fr = fch + c*241;
        #pragma unroll 4
        for (int p = 0; p < NPIX; p++) acc = fmaf(ar[p], fr[p], acc);
        size_t o = ((size_t)(t*32 + b))*1536 + 512 + c0 + c;
        split2(acc, cathi[o], catlo[o]);
    }
}

__global__ void out_kernel(const float* __restrict__ pred, float* __restrict__ out){
    int idx = blockIdx.x*256 + threadIdx.x;
    if (idx >= NB*LLAB*NCLASS) return;
    int n  = idx % NCLASS;
    int t1 = (idx / NCLASS) % LLAB;
    int b  = idx / (NCLASS*LLAB);
    size_t row = (size_t)((t1+1)*NB + b)*NPADC + n;
    float s = 0.f;
    #pragma unroll
    for (int z = 0; z < PRED_Z; z++) s += pred[(size_t)z*MDEC*NPADC + row];
    out[idx] = s;
}

static float* symaddr(const void* sym){
    void* p = nullptr;
    cudaGetSymbolAddress(&p, sym);
    return (float*)p;
}
static __nv_bfloat16* symaddr16(const void* sym){
    void* p = nullptr;
    cudaGetSymbolAddress(&p, sym);
    return (__nv_bfloat16*)p;
}

extern "C" void kernel_launch(void* const* d_in, const int* in_sizes, int n_in,
                              void* d_out, int out_size)
{
    const float* feat   = (const float*)d_in[0];
    const int*   label  = (const int*)  d_in[1];
    const float* vr     = (const float*)d_in[2];
    const float* e0_Wih = (const float*)d_in[3];
    const float* e0_Whh = (const float*)d_in[4];
    const float* e0_bih = (const float*)d_in[5];
    const float* e0_bhh = (const float*)d_in[6];
    const float* e1_Wih = (const float*)d_in[7];
    const float* e1_Whh = (const float*)d_in[8];
    const float* e1_bih = (const float*)d_in[9];
    const float* e1_bhh = (const float*)d_in[10];
    const float* enc_W  = (const float*)d_in[11];
    const float* enc_b  = (const float*)d_in[12];
    const float* q_W    = (const float*)d_in[13];
    const float* q_b    = (const float*)d_in[14];
    const float* k_W    = (const float*)d_in[15];
    const float* k_b    = (const float*)d_in[16];
    const float* s_W    = (const float*)d_in[17];
    const float* s_b    = (const float*)d_in[18];
    const float* emb    = (const float*)d_in[19];
    const float* d0_Wih = (const float*)d_in[20];
    const float* d0_Whh = (const float*)d_in[21];
    const float* d0_bih = (const float*)d_in[22];
    const float* d0_bhh = (const float*)d_in[23];
    const float* d1_Wih = (const float*)d_in[24];
    const float* d1_Whh = (const float*)d_in[25];
    const float* d1_bih = (const float*)d_in[26];
    const float* d1_bhh = (const float*)d_in[27];
    const float* pred_W = (const float*)d_in[28];
    const float* pred_b = (const float*)d_in[29];
    float* out = (float*)d_out;

    float* gbuf  = symaddr(g_gbuf);
    float* seqa  = symaddr(g_seqa);
    float* seqb  = symaddr(g_seqb);
    float* hid   = symaddr(g_hid);
    float* hol   = symaddr(g_hol);
    float* qbuf  = symaddr(g_q);
    float* kc    = symaddr(g_kc);
    float* pred  = symaddr(g_pred);
    float* score = symaddr(g_score);
    __nv_bfloat16* padhi = symaddr16(g_padhi);
    __nv_bfloat16* padlo = symaddr16(g_padlo);
    __nv_bfloat16* kwhi  = symaddr16(g_kwhi);
    __nv_bfloat16* kwlo  = symaddr16(g_kwlo);
    __nv_bfloat16* wihhi = symaddr16(g_wihhi);
    __nv_bfloat16* wihlo = symaddr16(g_wihlo);
    __nv_bfloat16* acthi = symaddr16(g_acthi);
    __nv_bfloat16* actlo = symaddr16(g_actlo);
    __nv_bfloat16* qwhi  = symaddr16(g_qwhi);
    __nv_bfloat16* qwlo  = symaddr16(g_qwlo);
    __nv_bfloat16* pwhi  = symaddr16(g_pwhi);
    __nv_bfloat16* pwlo  = symaddr16(g_pwlo);
    __nv_bfloat16* cathi = symaddr16(g_cathi);
    __nv_bfloat16* catlo = symaddr16(g_catlo);

    const int lstm_smem = (16*516 + 32*516 + 2*528 + 128) * 4;
    cudaFuncSetAttribute(lstm_layer, cudaFuncAttributeMaxDynamicSharedMemorySize, lstm_smem);
    const int score_smem = (27*512 + 512 + 512) * 4;
    cudaFuncSetAttribute(score_kernel, cudaFuncAttributeMaxDynamicSharedMemorySize, score_smem);
    const int af_smem = (TDEC*NPIX + 64*241) * 4;
    cudaFuncSetAttribute(attnfeat_kernel, cudaFuncAttributeMaxDynamicSharedMemorySize, af_smem);
    const int hol_smem = (32*513 + 4*512 + 256) * 4;
    cudaFuncSetAttribute(holistic_kernel, cudaFuncAttributeMaxDynamicSharedMemorySize, hol_smem);
    const int mma_smem = 2*STAGE_BYTES;
    cudaFuncSetAttribute(mma_gemm, cudaFuncAttributeMaxDynamicSharedMemorySize, mma_smem);
    const int w_smem = 2*WSTAGE_BYTES;
    cudaFuncSetAttribute(conv_gemm2, cudaFuncAttributeMaxDynamicSharedMemorySize, w_smem);
    cudaFuncSetAttribute(gemm_w, cudaFuncAttributeMaxDynamicSharedMemorySize, w_smem);
    const size_t WSZ = (size_t)2048*NCH;

    // my idx 3 = conv_gemm2 (profiled) — serial single stream (R13 shape)
    featv_kernel<<<(NB*NCH*WWW+255)/256, 256>>>(feat, acthi, actlo);                 // 0
    { dim3 g(4, NB*PADH); featpad_kernel<<<g, 256>>>(feat, padhi, padlo); }          // 1
    cvt_kw<<<(NCH*KCONV+255)/256, 256>>>(k_W, kwhi, kwlo);                           // 2
    { dim3 g(4, 60); conv_gemm2<<<g, 256, w_smem>>>(padhi, padlo, kwhi, kwlo,
                                kc, k_b); }                                          // 3
    { dim3 g((2048*NCH+255)/256, 4);
      cvt4<<<g, 256>>>(e0_Wih, e1_Wih, d0_Wih, d1_Wih, wihhi, wihlo); }              // 4
    { dim3 g(1024, 2); cvt2<<<g, 256>>>(q_W, pred_W, qwhi, qwlo, pwhi, pwlo); }      // 5

    // encoder
    { dim3 g(16, 10); gemm_w<<<g, 256, w_smem>>>(acthi, actlo, wihhi, wihlo,
                                gbuf, MENC, 2048, NCH, e0_bih, e0_bhh); }
    lstm_layer<<<LSTM_BLOCKS, 256, lstm_smem>>>(gbuf, e0_Whh, seqa, TENC, acthi, actlo);
    { dim3 g(16, 10); gemm_w<<<g, 256, w_smem>>>(acthi, actlo, wihhi + WSZ, wihlo + WSZ,
                                gbuf, MENC, 2048, NCH, e1_bih, e1_bhh); }
    lstm_layer<<<LSTM_BLOCKS, 256, lstm_smem>>>(gbuf, e1_Whh, seqb, TENC, nullptr, nullptr);
    holistic_kernel<<<128, 256, hol_smem>>>(seqb + (size_t)(TENC-1)*NB*NCH, enc_W, enc_b, hol);

    // decoder
    tok_kernel<<<MDEC, 256>>>(hol, emb, label, acthi, actlo);
    { dim3 g(16, 7); gemm_w<<<g, 256, w_smem>>>(acthi, actlo, wihhi + 2*WSZ, wihlo + 2*WSZ,
                                gbuf, MDEC, 2048, NCH, d0_bih, d0_bhh); }
    lstm_layer<<<LSTM_BLOCKS, 256, lstm_smem>>>(gbuf, d0_Whh, seqa, TDEC, acthi, actlo);
    { dim3 g(16, 7); gemm_w<<<g, 256, w_smem>>>(acthi, actlo, wihhi + 3*WSZ, wihlo + 3*WSZ,
                                gbuf, MDEC, 2048, NCH, d1_bih, d1_bhh); }
    lstm_layer<<<LSTM_BLOCKS, 256, lstm_smem>>>(gbuf, d1_Whh, hid, TDEC, acthi, actlo);

    // attention
    { dim3 g(8, 7, 1); mma_gemm<<<g, 256, mma_smem>>>(acthi, actlo, qwhi, qwlo,
                                qbuf, MDEC, NCH, NCH, NCH, q_b, nullptr); }
    { dim3 g(20, 32); score_kernel<<<g, 256, score_smem>>>(kc, qbuf, s_W, s_b, score); }
    softmax_kernel<<<NB, 256>>>(score, hid, hol, vr, cathi, catlo);
    { dim3 g(8, 32); attnfeat_kernel<<<g, 256, af_smem>>>(score, feat, cathi, catlo); }

    // prediction
    { dim3 g(2, 7, PRED_Z); mma_gemm<<<g, 256, mma_smem>>>(cathi, catlo, pwhi, pwlo,
                                pred, MDEC, NPADC, 1536, NCLASS, pred_b, nullptr); }
    out_kernel<<<(NB*LLAB*NCLASS+255)/256, 256>>>(pred, out);
}

// round 17
// speedup vs baseline: 1.1632x; 1.0236x over previous
#include <cuda_runtime.h>
#include <cuda_bf16.h>
#include <math.h>
#include <stdint.h>

#define NB 32
#define NCH 512
#define HHH 6
#define WWW 40
#define NPIX 240
#define NCLASS 97
#define NPADC 128
#define TENC 40
#define TDEC 27
#define LLAB 26
#define MENC 1280
#define MDEC 864
#define KCONV 4608
#define MCONV 7680
#define LSTM_BLOCKS 128
#define PRED_Z 4
#define PADW 42
#define PADH 8

__device__ float g_gbuf[MENC*2048];
__device__ float g_seqa[MENC*NCH];
__device__ float g_seqb[MENC*NCH];
__device__ float g_hid[MDEC*NCH];
__device__ float g_hol[NB*NCH];
__device__ float g_q[MDEC*NCH];
__device__ float g_kc[MCONV*NCH];
__device__ float g_pred[PRED_Z*MDEC*NPADC];
__device__ float g_score[NB*TDEC*NPIX];
__device__ __nv_bfloat16 g_padhi[NB*PADH*PADW*NCH];
__device__ __nv_bfloat16 g_padlo[NB*PADH*PADW*NCH];
__device__ __nv_bfloat16 g_kwhi[NCH*KCONV];
__device__ __nv_bfloat16 g_kwlo[NCH*KCONV];
__device__ __nv_bfloat16 g_wihhi[4*2048*NCH];
__device__ __nv_bfloat16 g_wihlo[4*2048*NCH];
__device__ __nv_bfloat16 g_acthi[MENC*NCH];
__device__ __nv_bfloat16 g_actlo[MENC*NCH];
__device__ __nv_bfloat16 g_qwhi[NCH*NCH];
__device__ __nv_bfloat16 g_qwlo[NCH*NCH];
__device__ __nv_bfloat16 g_pwhi[NCLASS*1536];
__device__ __nv_bfloat16 g_pwlo[NCLASS*1536];
__device__ __nv_bfloat16 g_cathi[MDEC*1536];
__device__ __nv_bfloat16 g_catlo[MDEC*1536];
__device__ unsigned g_cnt = 0;
__device__ unsigned g_gen = 0;

// ------------- helpers -------------
__device__ __forceinline__ float mufu_tanh(float x){
    float y; asm("tanh.approx.f32 %0, %1;" : "=f"(y) : "f"(x)); return y;
}
__device__ __forceinline__ float sigm(float x){ return 1.f/(1.f + expf(-x)); }
__device__ __forceinline__ void split2(float v, __nv_bfloat16& h, __nv_bfloat16& l){
    h = __float2bfloat16(v);
    l = __float2bfloat16(v - __bfloat162float(h));
}
__device__ __forceinline__ float psum2(unsigned long long v){
    return __uint_as_float((uint32_t)v) + __uint_as_float((uint32_t)(v >> 32));
}

#define MMA_B16(c, a, b0, b1) asm volatile( \
  "mma.sync.aligned.m16n8k16.row.col.f32.bf16.bf16.f32 " \
  "{%0,%1,%2,%3},{%4,%5,%6,%7},{%8,%9},{%0,%1,%2,%3};\n" \
  : "+f"((c)[0]),"+f"((c)[1]),"+f"((c)[2]),"+f"((c)[3]) \
  : "r"((a)[0]),"r"((a)[1]),"r"((a)[2]),"r"((a)[3]),"r"(b0),"r"(b1))

#define LDSM4(r, addr) asm volatile( \
  "ldmatrix.sync.aligned.m8n8.x4.shared.b16 {%0,%1,%2,%3}, [%4];" \
  : "=r"((r)[0]),"=r"((r)[1]),"=r"((r)[2]),"=r"((r)[3]) : "r"(addr))

#define FMA2(c, a, b) asm("fma.rn.f32x2 %0, %1, %2, %0;" : "+l"(c) : "l"(a), "l"(b))

__device__ __forceinline__ void cp16(uint32_t daddr, const void* src, int srcsz){
    asm volatile("cp.async.cg.shared.global [%0], [%1], 16, %2;\n"
                 :: "r"(daddr), "l"(src), "r"(srcsz));
}

__global__ void cvt4(const float* __restrict__ a0, const float* __restrict__ a1,
                     const float* __restrict__ a2, const float* __restrict__ a3,
                     __nv_bfloat16* __restrict__ hi, __nv_bfloat16* __restrict__ lo){
    int which = blockIdx.y;
    const float* src = which == 0 ? a0 : which == 1 ? a1 : which == 2 ? a2 : a3;
    int i = blockIdx.x*256 + threadIdx.x;
    if (i < 2048*NCH) {
        size_t o = (size_t)which*2048*NCH + i;
        split2(src[i], hi[o], lo[o]);
    }
}
__global__ void cvt2(const float* __restrict__ qW, const float* __restrict__ pW,
                     __nv_bfloat16* __restrict__ qhi, __nv_bfloat16* __restrict__ qlo,
                     __nv_bfloat16* __restrict__ phi, __nv_bfloat16* __restrict__ plo){
    int i = blockIdx.x*256 + threadIdx.x;
    if (blockIdx.y == 0) {
        if (i < NCH*NCH) split2(qW[i], qhi[i], qlo[i]);
    } else {
        if (i < NCLASS*1536) split2(pW[i], phi[i], plo[i]);
    }
}
__global__ void cvt_kw(const float* __restrict__ kW, __nv_bfloat16* __restrict__ hi,
                       __nv_bfloat16* __restrict__ lo){
    int i = blockIdx.x*256 + threadIdx.x;
    if (i >= NCH*KCONV) return;
    int o = i / KCONV, r = i - o*KCONV;
    int tap = r >> 9, cin = r & 511;
    split2(kW[(size_t)o*KCONV + cin*9 + tap], hi[i], lo[i]);
}
__global__ void featv_kernel(const float* __restrict__ feat,
                             __nv_bfloat16* __restrict__ hi, __nv_bfloat16* __restrict__ lo){
    int idx = blockIdx.x*256 + threadIdx.x;
    if (idx >= NB*NCH*WWW) return;
    int w = idx % WWW;
    int c = (idx / WWW) % NCH;
    int b = idx / (WWW*NCH);
    const float* p = feat + ((size_t)(b*NCH + c)*HHH)*WWW + w;
    float m = p[0];
    #pragma unroll
    for (int h = 1; h < HHH; h++) m = fmaxf(m, p[h*WWW]);
    size_t o = ((size_t)(w*NB + b))*NCH + c;
    split2(m, hi[o], lo[o]);
}

__global__ __launch_bounds__(256) void featpad_kernel(
    const float* __restrict__ feat,
    __nv_bfloat16* __restrict__ hi, __nv_bfloat16* __restrict__ lo)
{
    __shared__ float sm[128*41];
    const int tid = threadIdx.x;
    const int c0 = blockIdx.x * 128;
    const int b  = blockIdx.y >> 3;
    const int yy = blockIdx.y & 7;
    const int y  = yy - 1;
    const bool rowvalid = (y >= 0 && y < HHH);
    if (rowvalid) {
        for (int i = tid; i < 128*WWW; i += 256) {
            int c = i / WWW, x = i - c*WWW;
            sm[c*41 + x] = feat[((size_t)(b*NCH + c0 + c)*HHH + y)*WWW + x];
        }
    }
    __syncthreads();
    for (int i = tid; i < PADW*128; i += 256) {
        int xx = i >> 7, c = i & 127;
        int x = xx - 1;
        float v = (rowvalid && x >= 0 && x < WWW) ? sm[c*41 + x] : 0.f;
        size_t o = ((size_t)((b*PADH + yy)*PADW + xx))*NCH + c0 + c;
        split2(v, hi[o], lo[o]);
    }
}

// ---- tile geometry ----
#define SA_ELEM (128*40)
#define SB_ELEM (64*40)
#define STG_AH 0
#define STG_AL (SA_ELEM*2)
#define STG_BH (2*SA_ELEM*2)
#define STG_BL (2*SA_ELEM*2 + SB_ELEM*2)
#define STAGE_BYTES (2*SA_ELEM*2 + 2*SB_ELEM*2)
#define W_AH 0
#define W_AL (SA_ELEM*2)
#define W_BH (2*SA_ELEM*2)
#define W_BL (3*SA_ELEM*2)
#define WSTAGE_BYTES (4*SA_ELEM*2)

// implicit-conv GEMM: 128x128 tile, 2 CTA/SM. grid (4, 60).
__global__ __launch_bounds__(256, 2) void conv_gemm2(
    const __nv_bfloat16* __restrict__ Ahi, const __nv_bfloat16* __restrict__ Alo,
    const __nv_bfloat16* __restrict__ Bhi, const __nv_bfloat16* __restrict__ Blo,
    float* __restrict__ C, const float* __restrict__ bias)
{
    extern __shared__ __nv_bfloat16 smb[];
    const int tid = threadIdx.x;
    const int lane = tid & 31, warp = tid >> 5;
    const int wm = (warp & 3) << 5;
    const int wn = (warp >> 2) << 6;
    const int m0 = blockIdx.y * 128, n0 = blockIdx.x * 128;
    float acc[2][8][4];
    #pragma unroll
    for (int a = 0; a < 2; a++)
        #pragma unroll
        for (int b = 0; b < 8; b++)
            #pragma unroll
            for (int c = 0; c < 4; c++) acc[a][b][c] = 0.f;

    const uint32_t smemBase = (uint32_t)__cvta_generic_to_shared(smb);
    const int r0 = tid >> 2,          s0 = tid & 3;
    const int r1 = (tid + 256) >> 2,  s1 = (tid + 256) & 3;
    int gm0 = m0 + r0, gm1 = m0 + r1;
    int b0i = gm0 / NPIX, p0i = gm0 - b0i*NPIX, y0 = p0i / WWW, x0 = p0i - y0*WWW;
    int b1i = gm1 / NPIX, p1i = gm1 - b1i*NPIX, y1 = p1i / WWW, x1 = p1i - y1*WWW;
    const int pb0 = (b0i*PADH + y0)*PADW + x0;
    const int pb1 = (b1i*PADH + y1)*PADW + x1;
    const size_t rB0 = (size_t)(n0 + r0)*KCONV;
    const size_t rB1 = (size_t)(n0 + r1)*KCONV;
    const uint32_t d0 = (uint32_t)(r0*40 + s0*8)*2;
    const uint32_t d1 = (uint32_t)(r1*40 + s1*8)*2;
    const int o0 = s0*8, o1 = s1*8;

    const uint32_t aOff = (uint32_t)((wm + (lane & 15))*40 + (lane >> 4)*8)*2;
    const uint32_t bOff = (uint32_t)((wn + (lane & 7) + ((lane >> 4) & 1)*8)*40
                                     + ((lane >> 3) & 1)*8)*2;
    const int KT = KCONV >> 5;

    auto loadStage = [&](int it){
        int k0 = it << 5;
        uint32_t sb = smemBase + (it & 1) * WSTAGE_BYTES;
        int k0a = k0 + o0, k1a = k0 + o1;
        int tap0 = k0a >> 9, cin0 = k0a & 511;
        int tap1 = k1a >> 9, cin1 = k1a & 511;
        int td0 = (tap0*11) >> 5, td1 = (tap1*11) >> 5;
        int tofs0 = td0*PADW + (tap0 - td0*3);
        int tofs1 = td1*PADW + (tap1 - td1*3);
        size_t a0 = (size_t)(pb0 + tofs0)*NCH + cin0;
        size_t a1 = (size_t)(pb1 + tofs1)*NCH + cin1;
        cp16(sb + W_AH + d0, Ahi + a0, 16);
        cp16(sb + W_AH + d1, Ahi + a1, 16);
        cp16(sb + W_AL + d0, Alo + a0, 16);
        cp16(sb + W_AL + d1, Alo + a1, 16);
        cp16(sb + W_BH + d0, Bhi + rB0 + k0 + o0, 16);
        cp16(sb + W_BH + d1, Bhi + rB1 + k0 + o1, 16);
        cp16(sb + W_BL + d0, Blo + rB0 + k0 + o0, 16);
        cp16(sb + W_BL + d1, Blo + rB1 + k0 + o1, 16);
        asm volatile("cp.async.commit_group;\n");
    };

    loadStage(0);
    for (int it = 0; it < KT; it++) {
        if (it + 1 < KT) {
            loadStage(it + 1);
            asm volatile("cp.async.wait_group 1;\n");
        } else {
            asm volatile("cp.async.wait_group 0;\n");
        }
        __syncthreads();
        uint32_t sb = smemBase + (it & 1) * WSTAGE_BYTES;
        #pragma unroll
        for (int s = 0; s < 2; s++) {
            const uint32_t kB = s*32;
            uint32_t ah[2][4], al[2][4];
            LDSM4(ah[0], sb + W_AH + aOff + kB);
            LDSM4(ah[1], sb + W_AH + aOff + 16*80 + kB);
            LDSM4(al[0], sb + W_AL + aOff + kB);
            LDSM4(al[1], sb + W_AL + aOff + 16*80 + kB);
            #pragma unroll
            for (int ntp = 0; ntp < 4; ntp++) {
                uint32_t bh[4], bl[4];
                LDSM4(bh, sb + W_BH + bOff + ntp*16*80 + kB);
                LDSM4(bl, sb + W_BL + bOff + ntp*16*80 + kB);
                #pragma unroll
                for (int mt = 0; mt < 2; mt++) {
                    MMA_B16(acc[mt][2*ntp],   ah[mt], bh[0], bh[1]);
                    MMA_B16(acc[mt][2*ntp],   ah[mt], bl[0], bl[1]);
                    MMA_B16(acc[mt][2*ntp],   al[mt], bh[0], bh[1]);
                    MMA_B16(acc[mt][2*ntp+1], ah[mt], bh[2], bh[3]);
                    MMA_B16(acc[mt][2*ntp+1], ah[mt], bl[2], bl[3]);
                    MMA_B16(acc[mt][2*ntp+1], al[mt], bh[2], bh[3]);
                }
            }
        }
        __syncthreads();
    }
    const int r = lane >> 2, kq = (lane & 3) << 1;
    #pragma unroll
    for (int mt = 0; mt < 2; mt++) {
        #pragma unroll
        for (int nt = 0; nt < 8; nt++) {
            int m = m0 + wm + mt*16 + r;
            int n = n0 + wn + nt*8 + kq;
            float bv0 = bias[n], bv1 = bias[n+1];
            C[(size_t)m*NCH + n]       = acc[mt][nt][0] + bv0;
            C[(size_t)m*NCH + n + 1]   = acc[mt][nt][1] + bv1;
            C[(size_t)(m+8)*NCH + n]   = acc[mt][nt][2] + bv0;
            C[(size_t)(m+8)*NCH + n+1] = acc[mt][nt][3] + bv1;
        }
    }
}

// generic 128x128 GEMM (xW)
__global__ __launch_bounds__(256, 2) void gemm_w(
    const __nv_bfloat16* __restrict__ Ahi, const __nv_bfloat16* __restrict__ Alo,
    const __nv_bfloat16* __restrict__ Bhi, const __nv_bfloat16* __restrict__ Blo,
    float* __restrict__ C, int M, int N, int K,
    const float* __restrict__ bias1, const float* __restrict__ bias2)
{
    extern __shared__ __nv_bfloat16 smb[];
    const int tid = threadIdx.x;
    const int lane = tid & 31, warp = tid >> 5;
    const int wm = (warp & 3) << 5;
    const int wn = (warp >> 2) << 6;
    const int m0 = blockIdx.y * 128, n0 = blockIdx.x * 128;
    float acc[2][8][4];
    #pragma unroll
    for (int a = 0; a < 2; a++)
        #pragma unroll
        for (int b = 0; b < 8; b++)
            #pragma unroll
            for (int c = 0; c < 4; c++) acc[a][b][c] = 0.f;

    const uint32_t smemBase = (uint32_t)__cvta_generic_to_shared(smb);
    const int r0 = tid >> 2,          s0 = tid & 3;
    const int r1 = (tid + 256) >> 2,  s1 = (tid + 256) & 3;
    const int gm0 = m0 + r0, gm1 = m0 + r1;
    const int szA0 = (gm0 < M) ? 16 : 0;
    const int szA1 = (gm1 < M) ? 16 : 0;
    const size_t rA0 = (size_t)min(gm0, M-1)*K, rA1 = (size_t)min(gm1, M-1)*K;
    const size_t rB0 = (size_t)(n0 + r0)*K, rB1 = (size_t)(n0 + r1)*K;
    const uint32_t d0 = (uint32_t)(r0*40 + s0*8)*2;
    const uint32_t d1 = (uint32_t)(r1*40 + s1*8)*2;
    const int o0 = s0*8, o1 = s1*8;
    const uint32_t aOff = (uint32_t)((wm + (lane & 15))*40 + (lane >> 4)*8)*2;
    const uint32_t bOff = (uint32_t)((wn + (lane & 7) + ((lane >> 4) & 1)*8)*40
                                     + ((lane >> 3) & 1)*8)*2;
    const int KT = K >> 5;

    auto loadStage = [&](int it){
        int k0 = it << 5;
        uint32_t sb = smemBase + (it & 1) * WSTAGE_BYTES;
        cp16(sb + W_AH + d0, Ahi + rA0 + k0 + o0, szA0);
        cp16(sb + W_AH + d1, Ahi + rA1 + k0 + o1, szA1);
        cp16(sb + W_AL + d0, Alo + rA0 + k0 + o0, szA0);
        cp16(sb + W_AL + d1, Alo + rA1 + k0 + o1, szA1);
        cp16(sb + W_BH + d0, Bhi + rB0 + k0 + o0, 16);
        cp16(sb + W_BH + d1, Bhi + rB1 + k0 + o1, 16);
        cp16(sb + W_BL + d0, Blo + rB0 + k0 + o0, 16);
        cp16(sb + W_BL + d1, Blo + rB1 + k0 + o1, 16);
        asm volatile("cp.async.commit_group;\n");
    };

    loadStage(0);
    for (int it = 0; it < KT; it++) {
        if (it + 1 < KT) {
            loadStage(it + 1);
            asm volatile("cp.async.wait_group 1;\n");
        } else {
            asm volatile("cp.async.wait_group 0;\n");
        }
        __syncthreads();
        uint32_t sb = smemBase + (it & 1) * WSTAGE_BYTES;
        #pragma unroll
        for (int s = 0; s < 2; s++) {
            const uint32_t kB = s*32;
            uint32_t ah[2][4], al[2][4];
            LDSM4(ah[0], sb + W_AH + aOff + kB);
            LDSM4(ah[1], sb + W_AH + aOff + 16*80 + kB);
            LDSM4(al[0], sb + W_AL + aOff + kB);
            LDSM4(al[1], sb + W_AL + aOff + 16*80 + kB);
            #pragma unroll
            for (int ntp = 0; ntp < 4; ntp++) {
                uint32_t bh[4], bl[4];
                LDSM4(bh, sb + W_BH + bOff + ntp*16*80 + kB);
                LDSM4(bl, sb + W_BL + bOff + ntp*16*80 + kB);
                #pragma unroll
                for (int mt = 0; mt < 2; mt++) {
                    MMA_B16(acc[mt][2*ntp],   ah[mt], bh[0], bh[1]);
                    MMA_B16(acc[mt][2*ntp],   ah[mt], bl[0], bl[1]);
                    MMA_B16(acc[mt][2*ntp],   al[mt], bh[0], bh[1]);
                    MMA_B16(acc[mt][2*ntp+1], ah[mt], bh[2], bh[3]);
                    MMA_B16(acc[mt][2*ntp+1], ah[mt], bl[2], bl[3]);
                    MMA_B16(acc[mt][2*ntp+1], al[mt], bh[2], bh[3]);
                }
            }
        }
        __syncthreads();
    }
    const int r = lane >> 2, kq = (lane & 3) << 1;
    #pragma unroll
    for (int mt = 0; mt < 2; mt++) {
        #pragma unroll
        for (int nt = 0; nt < 8; nt++) {
            int m = m0 + wm + mt*16 + r;
            int n = n0 + wn + nt*8 + kq;
            float bv0 = 0.f, bv1 = 0.f;
            if (bias1) { bv0 += bias1[n]; bv1 += bias1[n+1]; }
            if (bias2) { bv0 += bias2[n]; bv1 += bias2[n+1]; }
            if (m < M) {
                C[(size_t)m*N + n]     = acc[mt][nt][0] + bv0;
                C[(size_t)m*N + n + 1] = acc[mt][nt][1] + bv1;
            }
            if (m + 8 < M) {
                C[(size_t)(m+8)*N + n]     = acc[mt][nt][2] + bv0;
                C[(size_t)(m+8)*N + n + 1] = acc[mt][nt][3] + bv1;
            }
        }
    }
}

// 128x64 GEMM (q, pred). B-row guard + split-K via gridDim.z.
__global__ __launch_bounds__(256) void mma_gemm(
    const __nv_bfloat16* __restrict__ Ahi, const __nv_bfloat16* __restrict__ Alo,
    const __nv_bfloat16* __restrict__ Bhi, const __nv_bfloat16* __restrict__ Blo,
    float* __restrict__ C, int M, int N, int K, int NBrows,
    const float* __restrict__ bias1, const float* __restrict__ bias2)
{
    extern __shared__ __nv_bfloat16 smb[];
    const int tid = threadIdx.x;
    const int lane = tid & 31, warp = tid >> 5;
    const int wm = (warp & 3) << 5;
    const int wn = (warp >> 2) << 5;
    const int m0 = blockIdx.y * 128, n0 = blockIdx.x * 64;
    const int Kc = K / gridDim.z;
    const int kbeg = blockIdx.z * Kc;
    float acc[2][4][4];
    #pragma unroll
    for (int a = 0; a < 2; a++)
        #pragma unroll
        for (int b = 0; b < 4; b++)
            #pragma unroll
            for (int c = 0; c < 4; c++) acc[a][b][c] = 0.f;

    const uint32_t smemBase = (uint32_t)__cvta_generic_to_shared(smb);
    const int ar0 = tid >> 2,         as0 = tid & 3;
    const int ar1 = (tid + 256) >> 2, as1 = (tid + 256) & 3;
    const int br  = tid >> 2,         bs  = tid & 3;
    const int gm0 = m0 + ar0, gm1 = m0 + ar1, gn = n0 + br;
    const int szA0 = (gm0 < M) ? 16 : 0;
    const int szA1 = (gm1 < M) ? 16 : 0;
    const int szB  = (gn < NBrows) ? 16 : 0;
    const size_t rA0 = (size_t)min(gm0, M-1)*K, rA1 = (size_t)min(gm1, M-1)*K;
    const size_t rB  = (size_t)min(gn, NBrows-1)*K;
    const uint32_t dA0 = (uint32_t)(ar0*40 + as0*8)*2;
    const uint32_t dA1 = (uint32_t)(ar1*40 + as1*8)*2;
    const uint32_t dB  = (uint32_t)(br*40 + bs*8)*2;
    const int oA0 = as0*8, oA1 = as1*8, oB = bs*8;
    const uint32_t aOff = (uint32_t)((wm + (lane & 15))*40 + (lane >> 4)*8)*2;
    const uint32_t bOff = (uint32_t)((wn + (lane & 7) + ((lane >> 4) & 1)*8)*40
                                     + ((lane >> 3) & 1)*8)*2;
    const int KT = Kc >> 5;
    {
        uint32_t sb = smemBase;
        cp16(sb + STG_AH + dA0, Ahi + rA0 + kbeg + oA0, szA0);
        cp16(sb + STG_AH + dA1, Ahi + rA1 + kbeg + oA1, szA1);
        cp16(sb + STG_AL + dA0, Alo + rA0 + kbeg + oA0, szA0);
        cp16(sb + STG_AL + dA1, Alo + rA1 + kbeg + oA1, szA1);
        cp16(sb + STG_BH + dB,  Bhi + rB  + kbeg + oB,  szB);
        cp16(sb + STG_BL + dB,  Blo + rB  + kbeg + oB,  szB);
        asm volatile("cp.async.commit_group;\n");
    }
    for (int it = 0; it < KT; it++) {
        if (it + 1 < KT) {
            int k0 = kbeg + ((it + 1) << 5);
            uint32_t sb = smemBase + ((it + 1) & 1) * STAGE_BYTES;
            cp16(sb + STG_AH + dA0, Ahi + rA0 + k0 + oA0, szA0);
            cp16(sb + STG_AH + dA1, Ahi + rA1 + k0 + oA1, szA1);
            cp16(sb + STG_AL + dA0, Alo + rA0 + k0 + oA0, szA0);
            cp16(sb + STG_AL + dA1, Alo + rA1 + k0 + oA1, szA1);
            cp16(sb + STG_BH + dB,  Bhi + rB  + k0 + oB,  szB);
            cp16(sb + STG_BL + dB,  Blo + rB  + k0 + oB,  szB);
            asm volatile("cp.async.commit_group;\n");
            asm volatile("cp.async.wait_group 1;\n");
        } else {
            asm volatile("cp.async.wait_group 0;\n");
        }
        __syncthreads();
        uint32_t sb = smemBase + (it & 1) * STAGE_BYTES;
        #pragma unroll
        for (int s = 0; s < 2; s++) {
            const uint32_t kB = s*32;
            uint32_t ah[2][4], al[2][4];
            LDSM4(ah[0], sb + STG_AH + aOff + kB);
            LDSM4(ah[1], sb + STG_AH + aOff + 16*80 + kB);
            LDSM4(al[0], sb + STG_AL + aOff + kB);
            LDSM4(al[1], sb + STG_AL + aOff + 16*80 + kB);
            #pragma unroll
            for (int ntp = 0; ntp < 2; ntp++) {
                uint32_t bh[4], bl[4];
                LDSM4(bh, sb + STG_BH + bOff + ntp*16*80 + kB);
                LDSM4(bl, sb + STG_BL + bOff + ntp*16*80 + kB);
                #pragma unroll
                for (int mt = 0; mt < 2; mt++) {
                    MMA_B16(acc[mt][2*ntp],   ah[mt], bh[0], bh[1]);
                    MMA_B16(acc[mt][2*ntp],   ah[mt], bl[0], bl[1]);
                    MMA_B16(acc[mt][2*ntp],   al[mt], bh[0], bh[1]);
                    MMA_B16(acc[mt][2*ntp+1], ah[mt], bh[2], bh[3]);
                    MMA_B16(acc[mt][2*ntp+1], ah[mt], bl[2], bl[3]);
                    MMA_B16(acc[mt][2*ntp+1], al[mt], bh[2], bh[3]);
                }
            }
        }
        __syncthreads();
    }
    float* Co = C + (size_t)blockIdx.z * M * N;
    const bool addb = (blockIdx.z == 0);
    const int r = lane >> 2, kq = (lane & 3) << 1;
    #pragma unroll
    for (int mt = 0; mt < 2; mt++) {
        #pragma unroll
        for (int nt = 0; nt < 4; nt++) {
            int m = m0 + wm + mt*16 + r;
            int n = n0 + wn + nt*8 + kq;
            float bv0 = 0.f, bv1 = 0.f;
            if (addb && bias1) {
                if (n < NBrows)     bv0 += bias1[n];
                if (n + 1 < NBrows) bv1 += bias1[n+1];
            }
            if (addb && bias2) {
                if (n < NBrows)     bv0 += bias2[n];
                if (n + 1 < NBrows) bv1 += bias2[n+1];
            }
            if (m < M) {
                Co[(size_t)m*N + n]     = acc[mt][nt][0] + bv0;
                Co[(size_t)m*N + n + 1] = acc[mt][nt][1] + bv1;
            }
            if (m + 8 < M) {
                Co[(size_t)(m+8)*N + n]     = acc[mt][nt][2] + bv0;
                Co[(size_t)(m+8)*N + n + 1] = acc[mt][nt][3] + bv1;
            }
        }
    }
}

__global__ __launch_bounds__(256) void holistic_kernel(
    const float* __restrict__ A, const float* __restrict__ W,
    const float* __restrict__ bias, float* __restrict__ C)
{
    extern __shared__ float sm[];
    float* sA = sm;
    float* sW = sm + 32*513;
    float* sP = sW + 4*512;
    const int tid = threadIdx.x;
    const int j0 = blockIdx.x * 4;
    for (int i = tid; i < 32*512; i += 256)
        sA[(i>>9)*513 + (i&511)] = A[i];
    for (int i = tid; i < 4*512; i += 256)
        sW[i] = W[(size_t)(j0 + (i>>9))*512 + (i&511)];
    __syncthreads();
    const int bb = tid & 31, jq = (tid>>5)&3, kh = tid>>7;
    const float* ar = sA + bb*513 + kh*256;
    const float* wr = sW + jq*512 + kh*256;
    float acc = 0.f;
    #pragma unroll 8
    for (int k = 0; k < 256; k++) acc = fmaf(ar[k], wr[k], acc);
    sP[tid] = acc;
    __syncthreads();
    if (kh == 0) C[bb*512 + j0 + jq] = sP[tid] + sP[tid+128] + bias[j0+jq];
}

// persistent LSTM layer v3: 8 batches/thread, split-K quarters
__global__ __launch_bounds__(256) void lstm_layer(
    const float* __restrict__ gpre, const float* __restrict__ Whh,
    float* __restrict__ seq, int T,
    __nv_bfloat16* __restrict__ ohi, __nv_bfloat16* __restrict__ olo)
{
    extern __shared__ float sm[];
    float* sW  = sm;                       // [16][516]
    float* sh  = sm + 16*516;              // [32][516]
    float* gex = sm + 16*516 + 32*516;     // [4][16][33]
    float* sc  = gex + 4*528;              // [128]
    const int tid = threadIdx.x;
    const int j0 = blockIdx.x * 4;
    #pragma unroll
    for (int rr = 0; rr < 16; rr++) {
        int grow = (rr & 3)*512 + j0 + (rr >> 2);
        for (int k = tid*4; k < 512; k += 1024) {
            float4 v = *(const float4*)(Whh + (size_t)grow*512 + k);
            *(float4*)&sW[rr*516 + k] = v;
        }
    }
    if (tid < 128) sc[tid] = 0.f;
    __syncthreads();
    const int kq   = tid >> 6;            // k-quarter 0..3
    const int t2   = tid & 63;
    const int row  = t2 & 15;             // gate-row 0..15
    const int bg   = t2 >> 4;             // batch group 0..3 (8 batches each)
    const int kb   = kq << 7;             // 0,128,256,384
    const int cu   = tid & 3, cb = tid >> 2;
    const int cj   = j0 + cu;
    for (int t = 0; t < T; t++) {
        float gpi = 0.f, gpf = 0.f, gpg = 0.f, gpo = 0.f;
        if (tid < 128) {
            const float* gp = gpre + ((size_t)t*NB + cb)*2048;
            gpi = gp[cj]; gpf = gp[512 + cj]; gpg = gp[1024 + cj]; gpo = gp[1536 + cj];
        }
        if (t > 0) {
            const float* hp = seq + (size_t)(t-1)*NB*NCH;
            #pragma unroll
            for (int j = 0; j < 16; j++) {
                int v = tid + j*256;
                int bb = v >> 7, k4 = (v & 127) << 2;
                float4 x = __ldcg((const float4*)(hp + bb*512 + k4));
                *(float4*)&sh[bb*516 + k4] = x;
            }
            __syncthreads();
            unsigned long long ax[8][2];
            #pragma unroll
            for (int j = 0; j < 8; j++) { ax[j][0] = 0ull; ax[j][1] = 0ull; }
            const float* wrow = sW + row*516 + kb;
            const float* hbase = sh + (bg*8)*516 + kb;
            #pragma unroll 2
            for (int i = 0; i < 32; i++) {
                int k = i*4;
                ulonglong2 w = *(const ulonglong2*)(wrow + k);
                #pragma unroll
                for (int j = 0; j < 8; j++) {
                    ulonglong2 h = *(const ulonglong2*)(hbase + j*516 + k);
                    FMA2(ax[j][0], w.x, h.x);
                    FMA2(ax[j][1], w.y, h.y);
                }
            }
            #pragma unroll
            for (int j = 0; j < 8; j++)
                gex[kq*528 + row*33 + bg*8 + j] = psum2(ax[j][0]) + psum2(ax[j][1]);
        } else {
            #pragma unroll
            for (int j = 0; j < 8; j++)
                gex[kq*528 + row*33 + bg*8 + j] = 0.f;
        }
        __syncthreads();
        if (tid < 128) {
            int r0 = cu*4;
            float gi = gex[r0*33 + cb]     + gex[528 + r0*33 + cb]
                     + gex[1056 + r0*33 + cb] + gex[1584 + r0*33 + cb] + gpi;
            float gf = gex[(r0+1)*33 + cb] + gex[528 + (r0+1)*33 + cb]
                     + gex[1056 + (r0+1)*33 + cb] + gex[1584 + (r0+1)*33 + cb] + gpf;
            float gg = gex[(r0+2)*33 + cb] + gex[528 + (r0+2)*33 + cb]
                     + gex[1056 + (r0+2)*33 + cb] + gex[1584 + (r0+2)*33 + cb] + gpg;
            float go = gex[(r0+3)*33 + cb] + gex[528 + (r0+3)*33 + cb]
                     + gex[1056 + (r0+3)*33 + cb] + gex[1584 + (r0+3)*33 + cb] + gpo;
            float c = sigm(gf)*sc[cu*32+cb] + sigm(gi)*tanhf(gg);
            sc[cu*32+cb] = c;
            float hv = sigm(go)*tanhf(c);
            size_t oo = (size_t)t*NB*NCH + cb*512 + cj;
            seq[oo] = hv;
            if (ohi) split2(hv, ohi[oo], olo[oo]);
        }
        if (t < T-1) {
            __syncthreads();
            if (tid == 0) {
                __threadfence();
                unsigned old = *((volatile unsigned*)&g_gen);
                __threadfence();
                unsigned n = atomicAdd(&g_cnt, 1u);
                if (n == LSTM_BLOCKS-1) {
                    g_cnt = 0;
                    __threadfence();
                    atomicAdd(&g_gen, 1u);
                } else {
                    while (*((volatile unsigned*)&g_gen) == old) { }
                }
            }
            __syncthreads();
        }
    }
}

__global__ void tok_kernel(const float* __restrict__ hol, const float* __restrict__ emb,
                           const int* __restrict__ label,
                           __nv_bfloat16* __restrict__ hi, __nv_bfloat16* __restrict__ lo){
    int row = blockIdx.x;
    int b = row & 31, t = row >> 5;
    const float* src = (t == 0) ? (hol + b*NCH)
                                : (emb + (size_t)label[b*LLAB + (t-1)]*NCH);
    for (int i = threadIdx.x; i < NCH; i += 256) {
        size_t o = (size_t)row*NCH + i;
        split2(src[i], hi[o], lo[o]);
    }
}

// scores: MUFU tanh
__global__ __launch_bounds__(256) void score_kernel(
    const float* __restrict__ kc, const float* __restrict__ qm,
    const float* __restrict__ sW, const float* __restrict__ sb,
    float* __restrict__ score)
{
    extern __shared__ float sm[];
    float* qs  = sm;
    float* sws = sm + 27*512;
    float* kcr = sws + 512;
    const int b  = blockIdx.y;
    const int p0 = blockIdx.x * 12;
    const int tid = threadIdx.x;
    const int lane = tid & 31, w = tid >> 5;
    for (int i = tid; i < 27*512; i += 256) {
        int t = i >> 9, c = i & 511;
        qs[i] = qm[((size_t)(t*32+b))*512 + c];
    }
    for (int i = tid; i < 512; i += 256) sws[i] = sW[i];
    __syncthreads();
    const float sbv = sb[0];
    for (int pp = 0; pp < 12; pp++) {
        int p = p0 + pp;
        for (int i = tid; i < 512; i += 256)
            kcr[i] = kc[((size_t)(b*NPIX + p))*512 + i];
        __syncthreads();
        for (int t = w; t < TDEC; t += 8) {
            float s = 0.f;
            const float* qrow = qs + t*512;
            #pragma unroll
            for (int i = 0; i < 16; i++) {
                int c = lane + i*32;
                s = fmaf(sws[c], mufu_tanh(kcr[c] + qrow[c]), s);
            }
            #pragma unroll
            for (int o = 16; o; o >>= 1) s += __shfl_xor_sync(0xffffffffu, s, o);
            if (lane == 0) score[((size_t)(b*TDEC) + t)*NPIX + p] = s + sbv;
        }
        __syncthreads();
    }
}

__global__ __launch_bounds__(256) void softmax_kernel(
    float* __restrict__ score, const float* __restrict__ hid,
    const float* __restrict__ hol, const float* __restrict__ vr,
    __nv_bfloat16* __restrict__ cathi, __nv_bfloat16* __restrict__ catlo)
{
    __shared__ float sc[TDEC*NPIX];
    const int b = blockIdx.x;
    const int tid = threadIdx.x;
    const int lane = tid & 31, w = tid >> 5;
    int vw = min(WWW, (int)ceilf(WWW * vr[b]));
    for (int i = tid; i < TDEC*NPIX; i += 256) {
        int p = i % NPIX;
        float v = score[(size_t)b*TDEC*NPIX + i];
        sc[i] = ((p % WWW) < vw) ? v : -1e30f;
    }
    __syncthreads();
    for (int t = w; t < TDEC; t += 8) {
        float m = -1e30f;
        for (int p = lane; p < NPIX; p += 32) m = fmaxf(m, sc[t*NPIX + p]);
        #pragma unroll
        for (int o = 16; o; o >>= 1) m = fmaxf(m, __shfl_xor_sync(0xffffffffu, m, o));
        float s = 0.f;
        for (int p = lane; p < NPIX; p += 32) {
            float e = __expf(sc[t*NPIX + p] - m);
            sc[t*NPIX + p] = e;
            s += e;
        }
        #pragma unroll
        for (int o = 16; o; o >>= 1) s += __shfl_xor_sync(0xffffffffu, s, o);
        float inv = 1.f / s;
        for (int p = lane; p < NPIX; p += 32)
            score[(size_t)b*TDEC*NPIX + t*NPIX + p] = sc[t*NPIX + p] * inv;
    }
    for (int i = tid; i < TDEC*512; i += 256) {
        int t = i >> 9, c = i & 511;
        size_t row = (size_t)(t*32 + b);
        split2(hid[row*512 + c], cathi[row*1536 + c], catlo[row*1536 + c]);
        split2(hol[b*512 + c], cathi[row*1536 + 1024 + c], catlo[row*1536 + 1024 + c]);
    }
}

__global__ __launch_bounds__(256) void attnfeat_kernel(
    const float* __restrict__ score, const float* __restrict__ feat,
    __nv_bfloat16* __restrict__ cathi, __nv_bfloat16* __restrict__ catlo)
{
    extern __shared__ float sm[];
    float* aw  = sm;
    float* fch = sm + TDEC*NPIX;
    const int b = blockIdx.y;
    const int c0 = blockIdx.x * 64;
    const int tid = threadIdx.x;
    for (int i = tid; i < TDEC*NPIX; i += 256)
        aw[i] = score[(size_t)b*TDEC*NPIX + i];
    for (int i = tid; i < 64*NPIX; i += 256) {
        int c = i / NPIX, p = i - c*NPIX;
        fch[c*241 + p] = feat[((size_t)(b*NCH + c0 + c))*NPIX + p];
    }
    __syncthreads();
    for (int task = tid; task < TDEC*64; task += 256) {
        int t = task >> 6, c = task & 63;
        float acc = 0.f;
        const float* ar = aw + t*NPIX;
        const float* fr = fch + c*241;
        #pragma unroll 4
        for (int p = 0; p < NPIX; p++) acc = fmaf(ar[p], fr[p], acc);
        size_t o = ((size_t)(t*32 + b))*1536 + 512 + c0 + c;
        split2(acc, cathi[o], catlo[o]);
    }
}

__global__ void out_kernel(const float* __restrict__ pred, float* __restrict__ out){
    int idx = blockIdx.x*256 + threadIdx.x;
    if (idx >= NB*LLAB*NCLASS) return;
    int n  = idx % NCLASS;
    int t1 = (idx / NCLASS) % LLAB;
    int b  = idx / (NCLASS*LLAB);
    size_t row = (size_t)((t1+1)*NB + b)*NPADC + n;
    float s = 0.f;
    #pragma unroll
    for (int z = 0; z < PRED_Z; z++) s += pred[(size_t)z*MDEC*NPADC + row];
    out[idx] = s;
}

static float* symaddr(const void* sym){
    void* p = nullptr;
    cudaGetSymbolAddress(&p, sym);
    return (float*)p;
}
static __nv_bfloat16* symaddr16(const void* sym){
    void* p = nullptr;
    cudaGetSymbolAddress(&p, sym);
    return (__nv_bfloat16*)p;
}

extern "C" void kernel_launch(void* const* d_in, const int* in_sizes, int n_in,
                              void* d_out, int out_size)
{
    const float* feat   = (const float*)d_in[0];
    const int*   label  = (const int*)  d_in[1];
    const float* vr     = (const float*)d_in[2];
    const float* e0_Wih = (const float*)d_in[3];
    const float* e0_Whh = (const float*)d_in[4];
    const float* e0_bih = (const float*)d_in[5];
    const float* e0_bhh = (const float*)d_in[6];
    const float* e1_Wih = (const float*)d_in[7];
    const float* e1_Whh = (const float*)d_in[8];
    const float* e1_bih = (const float*)d_in[9];
    const float* e1_bhh = (const float*)d_in[10];
    const float* enc_W  = (const float*)d_in[11];
    const float* enc_b  = (const float*)d_in[12];
    const float* q_W    = (const float*)d_in[13];
    const float* q_b    = (const float*)d_in[14];
    const float* k_W    = (const float*)d_in[15];
    const float* k_b    = (const float*)d_in[16];
    const float* s_W    = (const float*)d_in[17];
    const float* s_b    = (const float*)d_in[18];
    const float* emb    = (const float*)d_in[19];
    const float* d0_Wih = (const float*)d_in[20];
    const float* d0_Whh = (const float*)d_in[21];
    const float* d0_bih = (const float*)d_in[22];
    const float* d0_bhh = (const float*)d_in[23];
    const float* d1_Wih = (const float*)d_in[24];
    const float* d1_Whh = (const float*)d_in[25];
    const float* d1_bih = (const float*)d_in[26];
    const float* d1_bhh = (const float*)d_in[27];
    const float* pred_W = (const float*)d_in[28];
    const float* pred_b = (const float*)d_in[29];
    float* out = (float*)d_out;

    float* gbuf  = symaddr(g_gbuf);
    float* seqa  = symaddr(g_seqa);
    float* seqb  = symaddr(g_seqb);
    float* hid   = symaddr(g_hid);
    float* hol   = symaddr(g_hol);
    float* qbuf  = symaddr(g_q);
    float* kc    = symaddr(g_kc);
    float* pred  = symaddr(g_pred);
    float* score = symaddr(g_score);
    __nv_bfloat16* padhi = symaddr16(g_padhi);
    __nv_bfloat16* padlo = symaddr16(g_padlo);
    __nv_bfloat16* kwhi  = symaddr16(g_kwhi);
    __nv_bfloat16* kwlo  = symaddr16(g_kwlo);
    __nv_bfloat16* wihhi = symaddr16(g_wihhi);
    __nv_bfloat16* wihlo = symaddr16(g_wihlo);
    __nv_bfloat16* acthi = symaddr16(g_acthi);
    __nv_bfloat16* actlo = symaddr16(g_actlo);
    __nv_bfloat16* qwhi  = symaddr16(g_qwhi);
    __nv_bfloat16* qwlo  = symaddr16(g_qwlo);
    __nv_bfloat16* pwhi  = symaddr16(g_pwhi);
    __nv_bfloat16* pwlo  = symaddr16(g_pwlo);
    __nv_bfloat16* cathi = symaddr16(g_cathi);
    __nv_bfloat16* catlo = symaddr16(g_catlo);

    const int lstm_smem = (16*516 + 32*516 + 4*528 + 128) * 4;
    cudaFuncSetAttribute(lstm_layer, cudaFuncAttributeMaxDynamicSharedMemorySize, lstm_smem);
    const int score_smem = (27*512 + 512 + 512) * 4;
    cudaFuncSetAttribute(score_kernel, cudaFuncAttributeMaxDynamicSharedMemorySize, score_smem);
    const int af_smem = (TDEC*NPIX + 64*241) * 4;
    cudaFuncSetAttribute(attnfeat_kernel, cudaFuncAttributeMaxDynamicSharedMemorySize, af_smem);
    const int hol_smem = (32*513 + 4*512 + 256) * 4;
    cudaFuncSetAttribute(holistic_kernel, cudaFuncAttributeMaxDynamicSharedMemorySize, hol_smem);
    const int mma_smem = 2*STAGE_BYTES;
    cudaFuncSetAttribute(mma_gemm, cudaFuncAttributeMaxDynamicSharedMemorySize, mma_smem);
    const int w_smem = 2*WSTAGE_BYTES;
    cudaFuncSetAttribute(conv_gemm2, cudaFuncAttributeMaxDynamicSharedMemorySize, w_smem);
    cudaFuncSetAttribute(gemm_w, cudaFuncAttributeMaxDynamicSharedMemorySize, w_smem);
    const size_t WSZ = (size_t)2048*NCH;

    // serial single stream (R16 shape); idx 3 = conv (profiled)
    featv_kernel<<<(NB*NCH*WWW+255)/256, 256>>>(feat, acthi, actlo);                 // 0
    { dim3 g(4, NB*PADH); featpad_kernel<<<g, 256>>>(feat, padhi, padlo); }          // 1
    cvt_kw<<<(NCH*KCONV+255)/256, 256>>>(k_W, kwhi, kwlo);                           // 2
    { dim3 g(4, 60); conv_gemm2<<<g, 256, w_smem>>>(padhi, padlo, kwhi, kwlo,
                                kc, k_b); }                                          // 3
    { dim3 g((2048*NCH+255)/256, 4);
      cvt4<<<g, 256>>>(e0_Wih, e1_Wih, d0_Wih, d1_Wih, wihhi, wihlo); }              // 4
    { dim3 g(1024, 2); cvt2<<<g, 256>>>(q_W, pred_W, qwhi, qwlo, pwhi, pwlo); }      // 5

    // encoder
    { dim3 g(16, 10); gemm_w<<<g, 256, w_smem>>>(acthi, actlo, wihhi, wihlo,
                                gbuf, MENC, 2048, NCH, e0_bih, e0_bhh); }
    lstm_layer<<<LSTM_BLOCKS, 256, lstm_smem>>>(gbuf, e0_Whh, seqa, TENC, acthi, actlo);
    { dim3 g(16, 10); gemm_w<<<g, 256, w_smem>>>(acthi, actlo, wihhi + WSZ, wihlo + WSZ,
                                gbuf, MENC, 2048, NCH, e1_bih, e1_bhh); }
    lstm_layer<<<LSTM_BLOCKS, 256, lstm_smem>>>(gbuf, e1_Whh, seqb, TENC, nullptr, nullptr);
    holistic_kernel<<<128, 256, hol_smem>>>(seqb + (size_t)(TENC-1)*NB*NCH, enc_W, enc_b, hol);

    // decoder
    tok_kernel<<<MDEC, 256>>>(hol, emb, label, acthi, actlo);
    { dim3 g(16, 7); gemm_w<<<g, 256, w_smem>>>(acthi, actlo, wihhi + 2*WSZ, wihlo + 2*WSZ,
                                gbuf, MDEC, 2048, NCH, d0_bih, d0_bhh); }
    lstm_layer<<<LSTM_BLOCKS, 256, lstm_smem>>>(gbuf, d0_Whh, seqa, TDEC, acthi, actlo);
    { dim3 g(16, 7); gemm_w<<<g, 256, w_smem>>>(acthi, actlo, wihhi + 3*WSZ, wihlo + 3*WSZ,
                                gbuf, MDEC, 2048, NCH, d1_bih, d1_bhh); }
    lstm_layer<<<LSTM_BLOCKS, 256, lstm_smem>>>(gbuf, d1_Whh, hid, TDEC, acthi, actlo);

    // attention
    { dim3 g(8, 7, 1); mma_gemm<<<g, 256, mma_smem>>>(acthi, actlo, qwhi, qwlo,
                                qbuf, MDEC, NCH, NCH, NCH, q_b, nullptr); }
    { dim3 g(20, 32); score_kernel<<<g, 256, score_smem>>>(kc, qbuf, s_W, s_b, score); }
    softmax_kernel<<<NB, 256>>>(score, hid, hol, vr, cathi, catlo);
    { dim3 g(8, 32); attnfeat_kernel<<<g, 256, af_smem>>>(score, feat, cathi, catlo); }

    // prediction
    { dim3 g(2, 7, PRED_Z); mma_gemm<<<g, 256, mma_smem>>>(cathi, catlo, pwhi, pwlo,
                                pred, MDEC, NPADC, 1536, NCLASS, pred_b, nullptr); }
    out_kernel<<<(NB*LLAB*NCLASS+255)/256, 256>>>(pred, out);
}